// round 10
// baseline (speedup 1.0000x reference)
#include <cuda_runtime.h>
#include <math.h>

// Problem constants
#define BB   32
#define SSL  1024
#define SQQ  32
#define NNN  128
#define DINN 128
#define HHH  256
#define AAA  100
#define OOO  2000
#define G3H  768
#define FEAT 1794   // 7*H + 2

// ---------------- scratch offsets (floats) in one big device buffer ----------
#define OFF_GI    0UL          // 1024*768*32
#define OFF_GIQ   25165824UL   // 32*768*32
#define OFF_H     25952256UL   // 2*32*256 ping-pong h, [pp][b][k]
#define OFF_COUT  25968640UL   // 1024*256*32  [t][k][b]
#define OFF_QOUT  34357248UL   // 32*256*32
#define OFF_QH    34619392UL   // 32*256
#define OFF_HTC   34627584UL   // 32*256
#define OFF_CSEL  34635776UL   // 32*128*256
#define OFF_CW    35684352UL   // 32*128*256
#define OFF_DOTQ  36732928UL   // 4096
#define OFF_DOTM  36737024UL   // 4096
#define OFF_T0    36741120UL   // 4096*100
#define OFF_M     37150720UL   // 32*256
#define OFF_SC    37158912UL   // 4096
#define OFF_P     37163008UL   // 4096
#define OFF_E     37167104UL   // 32*256
#define OFF_MSQ   37175296UL   // 32*256
#define OFF_Y     37183488UL   // 32*2000
#define OFF_W1T   37247488UL   // 1794*128
#define OFF_BT    37477120UL   // 32*100
#define OFF_WTAI  37480320UL   // 2256*768
#define OFF_WTAH  39212928UL   // 256*768
#define OFF_WTMI  39409536UL   // 256*768
#define OFF_WTMH  39606144UL   // 256*768
#define OFF_OWT   39802752UL   // 256*2000
#define OFF_GIA   40314752UL   // 32*768
#define OFF_GHA   40339328UL   // 32*768
#define TOTALF    40363904UL

__device__ __align__(16) float g_buf[TOTALF];
__device__ __align__(64) int g_flag[128];   // per-block step counters

// ---------------- zero flags --------------------------------------------------
__global__ void zeroflags_kernel(int* flags) { flags[threadIdx.x] = 0; }

// ---------------- gi = x @ w_ih^T + b_ih  ->  out[t][row][b] -----------------
// grid (S, 4): blockIdx.y selects a 192-row chunk. 4-row register blocking.
__global__ void __launch_bounds__(256) gi_kernel(
    const float* __restrict__ x, const float* __restrict__ w,
    const float* __restrict__ bias, float* __restrict__ out, int S)
{
    const int t = blockIdx.x;
    const int rbase = blockIdx.y * 192;
    __shared__ float4 xs4[32][33];   // [b][k4]
    for (int idx = threadIdx.x; idx < 1024; idx += 256) {
        int b = idx >> 5, k4 = idx & 31;
        xs4[b][k4] = __ldg(((const float4*)x) + ((size_t)b * S + t) * 32 + k4);
    }
    __syncthreads();
    const int b = threadIdx.x & 31, w0 = threadIdx.x >> 5;
    for (int r = rbase + w0 * 4; r < rbase + 192; r += 32) {
        const float4* wr0 = (const float4*)(w + (size_t)r * DINN);
        const float4* wr1 = wr0 + 32;
        const float4* wr2 = wr0 + 64;
        const float4* wr3 = wr0 + 96;
        float s[4][4];
        #pragma unroll
        for (int i = 0; i < 4; ++i)
            #pragma unroll
            for (int jj = 0; jj < 4; ++jj) s[i][jj] = 0.f;
        #pragma unroll
        for (int k4 = 0; k4 < 32; ++k4) {
            float4 xv = xs4[b][k4];
            float4 w0v = __ldg(wr0 + k4), w1v = __ldg(wr1 + k4);
            float4 w2v = __ldg(wr2 + k4), w3v = __ldg(wr3 + k4);
            s[0][0] += w0v.x * xv.x; s[0][1] += w0v.y * xv.y; s[0][2] += w0v.z * xv.z; s[0][3] += w0v.w * xv.w;
            s[1][0] += w1v.x * xv.x; s[1][1] += w1v.y * xv.y; s[1][2] += w1v.z * xv.z; s[1][3] += w1v.w * xv.w;
            s[2][0] += w2v.x * xv.x; s[2][1] += w2v.y * xv.y; s[2][2] += w2v.z * xv.z; s[2][3] += w2v.w * xv.w;
            s[3][0] += w3v.x * xv.x; s[3][1] += w3v.y * xv.y; s[3][2] += w3v.z * xv.z; s[3][3] += w3v.w * xv.w;
        }
        #pragma unroll
        for (int i = 0; i < 4; ++i)
            out[((size_t)t * G3H + r + i) * BB + b] =
                __ldg(bias + r + i) + (s[i][0] + s[i][1]) + (s[i][2] + s[i][3]);
    }
}

// ---------------- persistent GRU recurrence (128 blocks x 128 threads) -------
// h layout: hbuf[pp][b][k]. Block j owns h cols 2j, 2j+1 (x3 gates).
// Flag protocol: producer j stores flag[j]=t+1 after its step-t writes
// (release = fence+store, NO atomics). Consumer warp 0 polls all 128 flags
// with one coalesced int4/lane read per round. Ping-pong makes one
// sync point per step sufficient.
__global__ void __launch_bounds__(128, 1) rec_kernel(
    const float* __restrict__ gi, const float* __restrict__ whh,
    const float* __restrict__ bhh, int S,
    float* __restrict__ hbuf, float* __restrict__ cout,
    float* __restrict__ finalh, int* __restrict__ flags)
{
    const int j = blockIdx.x, c0 = 2 * j;
    const int tid = threadIdx.x, wid = tid >> 5, lane = tid & 31;
    const int cb = wid & 1, kh = wid >> 1;

    __shared__ float4 hs4[32 * 65];          // [b][65 float4], stride 260 words (≡4 mod 32: conflict-free)
    __shared__ float  wss[6][HHH];           // [cb*3+g][k]
    __shared__ float  part[2][2][3][32];     // [cb][kh][g][b]
    __shared__ float  gis[6][32];            // [cb*3+g][b]
    __shared__ float  bsh[6];

    for (int i = tid; i < 6 * HHH; i += 128) {
        int d = i >> 8, k = i & 255;
        int cbb = d / 3, g = d % 3;
        wss[d][k] = whh[(size_t)(g * HHH + c0 + cbb) * HHH + k];
    }
    if (tid < 6) bsh[tid] = bhh[(tid % 3) * HHH + c0 + tid / 3];
    __syncthreads();

    int pp = 0;
    for (int t = 0; t < S; ++t) {
        // prefetch gi (independent of recurrence state) — issues early
        float g0 = __ldg(gi + ((size_t)t * G3H + (wid % 3) * HHH + c0 + wid / 3) * BB + lane);
        float g1 = 0.f;
        if (tid < 64) {
            int d1 = wid + 4;
            g1 = __ldg(gi + ((size_t)t * G3H + (d1 % 3) * HHH + c0 + d1 / 3) * BB + lane);
        }

        // acquire: wait until every block has finished step t-1
        if (t > 0) {
            if (tid < 32) {
                const int4* f4 = (const int4*)flags;
                while (true) {
                    int4 v = __ldcg(f4 + lane);   // 32 lanes x int4 = all 128 flags
                    bool ok = (v.x >= t) && (v.y >= t) && (v.z >= t) && (v.w >= t);
                    if (__all_sync(0xffffffffu, ok)) break;
#if __CUDA_ARCH__ >= 700
                    __nanosleep(20);
#endif
                }
                __threadfence();
            }
            __syncthreads();
        }

        gis[wid][lane] = g0;
        if (tid < 64) gis[wid + 4][lane] = g1;

        // stage h[pp] (32 KB) as [b][k], L2-coherent
        const float4* src = (const float4*)(hbuf + pp * (BB * HHH));
        #pragma unroll
        for (int it = 0; it < 16; ++it) {
            int idx = tid + it * 128;
            hs4[(idx >> 6) * 65 + (idx & 63)] = __ldcg(src + idx);
        }
        __syncthreads();

        // register-blocked 3-gate dot: each h float4 feeds 12 FMAs
        const float4* hp = &hs4[lane * 65 + kh * 32];
        const float4* wr = (const float4*)&wss[cb * 3 + 0][kh * 128];
        const float4* wz = (const float4*)&wss[cb * 3 + 1][kh * 128];
        const float4* wn = (const float4*)&wss[cb * 3 + 2][kh * 128];
        float r0 = 0, r1 = 0, r2 = 0, r3 = 0;
        float z0 = 0, z1 = 0, z2 = 0, z3 = 0;
        float n0 = 0, n1 = 0, n2 = 0, n3 = 0;
        #pragma unroll
        for (int k4 = 0; k4 < 32; ++k4) {
            float4 hv = hp[k4];
            float4 wa = wr[k4], wb = wz[k4], wc = wn[k4];
            r0 += wa.x * hv.x; r1 += wa.y * hv.y; r2 += wa.z * hv.z; r3 += wa.w * hv.w;
            z0 += wb.x * hv.x; z1 += wb.y * hv.y; z2 += wb.z * hv.z; z3 += wb.w * hv.w;
            n0 += wc.x * hv.x; n1 += wc.y * hv.y; n2 += wc.z * hv.z; n3 += wc.w * hv.w;
        }
        part[cb][kh][0][lane] = (r0 + r1) + (r2 + r3);
        part[cb][kh][1][lane] = (z0 + z1) + (z2 + z3);
        part[cb][kh][2][lane] = (n0 + n1) + (n2 + n3);
        __syncthreads();

        if (tid < 64) {
            int cc = tid >> 5, b = tid & 31, col = c0 + cc;
            float hr  = part[cc][0][0][b] + part[cc][1][0][b] + bsh[cc * 3 + 0];
            float hz  = part[cc][0][1][b] + part[cc][1][1][b] + bsh[cc * 3 + 1];
            float hn  = part[cc][0][2][b] + part[cc][1][2][b] + bsh[cc * 3 + 2];
            float rg = 1.f / (1.f + expf(-(gis[cc * 3 + 0][b] + hr)));
            float zg = 1.f / (1.f + expf(-(gis[cc * 3 + 1][b] + hz)));
            float ng = tanhf(gis[cc * 3 + 2][b] + rg * hn);
            float hold = ((const float*)hs4)[b * 260 + col];
            float hnew = (1.f - zg) * ng + zg * hold;
            hbuf[(pp ^ 1) * (BB * HHH) + b * HHH + col] = hnew;
            cout[((size_t)t * HHH + col) * BB + b] = hnew;   // [t][k][b] coalesced
            if (t == S - 1) finalh[b * HHH + col] = hnew;
        }
        __syncthreads();
        // release: publish step t completion (parallel per-block stores, no atomics)
        if (tid == 0) { __threadfence(); ((volatile int*)flags)[j] = t + 1; }
        pp ^= 1;
    }
}

// ---------------- transpose src[R][K] -> dst[K][R] ---------------------------
__global__ void transpose_kernel(const float* __restrict__ src, float* __restrict__ dst,
                                 int R, int K)
{
    __shared__ float tile[32][33];
    int k0 = blockIdx.x * 32, r0 = blockIdx.y * 32;
    int lx = threadIdx.x, ly = threadIdx.y;   // 32 x 8
    for (int i = ly; i < 32; i += 8) {
        int r = r0 + i, k = k0 + lx;
        tile[i][lx] = (r < R && k < K) ? src[(size_t)r * K + k] : 0.f;
    }
    __syncthreads();
    for (int i = ly; i < 32; i += 8) {
        int k = k0 + i, r = r0 + lx;
        if (k < K && r < R) dst[(size_t)k * R + r] = tile[lx][i];
    }
}

// ---------------- transpose att_w1 -> w1t[f][a] padded to 128 ----------------
__global__ void w1t_kernel(const float* __restrict__ w1, float* __restrict__ w1t)
{
    int idx = blockIdx.x * 256 + threadIdx.x;
    if (idx >= FEAT * 128) return;
    int f = idx >> 7, a = idx & 127;
    w1t[idx] = (a < AAA) ? w1[a * FEAT + f] : 0.f;
}

// ---------------- gather c_sel (from [t][k][b]) + cw = c_sel @ att_weight ----
__global__ void __launch_bounds__(256) cwgather_kernel(
    const float* __restrict__ cout, const int* __restrict__ cindex,
    const float* __restrict__ attw, float* __restrict__ csel, float* __restrict__ cw)
{
    const int r0 = blockIdx.x * 16;
    const int b  = r0 >> 7;
    const int tid = threadIdx.x;
    __shared__ float cs[16][HHH];
    __shared__ int ti[16];
    if (tid < 16) ti[tid] = cindex[b * NNN + ((r0 + tid) & 127)];
    __syncthreads();
    for (int idx = tid; idx < 16 * HHH; idx += 256) {
        int r = idx >> 8, k = idx & 255;
        float v = cout[((size_t)ti[r] * HHH + k) * BB + b];
        cs[r][k] = v;
        csel[(size_t)(r0 + r) * HHH + k] = v;
    }
    __syncthreads();
    float acc[16];
    #pragma unroll
    for (int r = 0; r < 16; ++r) acc[r] = 0.f;
    const int jcol = tid;
    for (int k = 0; k < HHH; ++k) {
        float wk = __ldg(attw + k * HHH + jcol);
        #pragma unroll
        for (int r = 0; r < 16; ++r) acc[r] += cs[r][k] * wk;
    }
    #pragma unroll
    for (int r = 0; r < 16; ++r) cw[(size_t)(r0 + r) * HHH + jcol] = acc[r];
}

// ---------------- per-row dot with per-b vector ------------------------------
__global__ void dot_kernel(const float* __restrict__ mat, const float* __restrict__ vec,
                           float* __restrict__ out)
{
    const int row = blockIdx.x;
    const int b = row >> 7;
    const int tid = threadIdx.x;   // 64
    const float4* mr = (const float4*)(mat + (size_t)row * HHH);
    const float4* vr = (const float4*)(vec + b * HHH);
    float4 a = mr[tid], v = vr[tid];
    float s = a.x * v.x + a.y * v.y + a.z * v.z + a.w * v.w;
    for (int o = 16; o; o >>= 1) s += __shfl_xor_sync(0xffffffffu, s, o);
    __shared__ float sm[2];
    if ((tid & 31) == 0) sm[tid >> 5] = s;
    __syncthreads();
    if (tid == 0) out[row] = sm[0] + sm[1];
}

// ---------------- bterm[b][a] = (b1?) + v[b] . w1t_cols(off..off+256) --------
__global__ void bterm_kernel(const float* __restrict__ v, const float* __restrict__ w1t,
                             const float* __restrict__ b1, int off, float* __restrict__ out)
{
    const int b = blockIdx.x, a = threadIdx.x;   // 128 threads
    __shared__ float vs[HHH];
    for (int i = a; i < HHH; i += 128) vs[i] = v[b * HHH + i];
    __syncthreads();
    float a0 = 0, a1 = 0, a2 = 0, a3 = 0;
    for (int k = 0; k < HHH; k += 4) {
        a0 += vs[k]     * w1t[(off + k) * 128 + a];
        a1 += vs[k + 1] * w1t[(off + k + 1) * 128 + a];
        a2 += vs[k + 2] * w1t[(off + k + 2) * 128 + a];
        a3 += vs[k + 3] * w1t[(off + k + 3) * 128 + a];
    }
    if (a < AAA) out[b * AAA + a] = (b1 ? __ldg(b1 + a) : 0.f) + (a0 + a1) + (a2 + a3);
}

// ---------------- attention projection (T0 precompute or hop+score) ----------
template <bool USEC, bool SCORE>
__global__ void __launch_bounds__(128) attproj_kernel(
    const float* __restrict__ csel, const float* __restrict__ vvec,
    const float* __restrict__ base, const float* __restrict__ dotv,
    const float* __restrict__ w1t, const float* __restrict__ bterm,
    int o2, int o3, int dotcol,
    const float* __restrict__ w2, const float* __restrict__ b2,
    float* __restrict__ outT0, float* __restrict__ outScores)
{
    const int r0 = blockIdx.x * 16;
    const int b  = r0 >> 7;
    const int tid = threadIdx.x;
    __shared__ float cs[16][HHH];
    __shared__ float vs[HHH];
    __shared__ float tvs[16][128];
    for (int idx = tid; idx < 16 * HHH; idx += 128)
        cs[idx >> 8][idx & 255] = csel[(size_t)(r0 + (idx >> 8)) * HHH + (idx & 255)];
    for (int idx = tid; idx < HHH; idx += 128) vs[idx] = vvec[b * HHH + idx];
    __syncthreads();

    const int a = tid;
    const bool va = a < AAA;
    float bt = va ? bterm[b * AAA + a] : 0.f;
    float wd = w1t[dotcol * 128 + a];
    float acc[16];
    #pragma unroll
    for (int r = 0; r < 16; ++r) {
        float v0 = bt + dotv[r0 + r] * wd;
        if (SCORE && va) v0 += base[(size_t)(r0 + r) * AAA + a];
        acc[r] = v0;
    }
    for (int k = 0; k < HHH; ++k) {
        float f1 = USEC ? w1t[k * 128 + a] : 0.f;
        float f2 = w1t[(o2 + k) * 128 + a];
        float f3 = w1t[(o3 + k) * 128 + a];
        float vk = vs[k];
        #pragma unroll
        for (int r = 0; r < 16; ++r) {
            float c = cs[r][k];
            acc[r] += (c * vk) * f2 + fabsf(c - vk) * f3;
            if (USEC) acc[r] += c * f1;
        }
    }
    if (!SCORE) {
        if (va) {
            #pragma unroll
            for (int r = 0; r < 16; ++r) outT0[(size_t)(r0 + r) * AAA + a] = acc[r];
        }
    } else {
        float w2a = va ? __ldg(w2 + a) : 0.f;
        #pragma unroll
        for (int r = 0; r < 16; ++r) tvs[r][a] = va ? tanhf(acc[r]) * w2a : 0.f;
        __syncthreads();
        int wq = tid >> 5, ln = tid & 31;
        #pragma unroll
        for (int rr = 0; rr < 4; ++rr) {
            int row = wq * 4 + rr;
            float s = tvs[row][ln] + tvs[row][ln + 32] + tvs[row][ln + 64] + tvs[row][ln + 96];
            for (int o = 16; o; o >>= 1) s += __shfl_xor_sync(0xffffffffu, s, o);
            if (ln == 0) outScores[r0 + row] = s + __ldg(b2);
        }
    }
}

// ---------------- masked softmax over N=128 ----------------------------------
__global__ void softmaxN_kernel(const float* __restrict__ scores, const int* __restrict__ lenc,
                                float* __restrict__ p, float* __restrict__ attout)
{
    const int b = blockIdx.x, n = threadIdx.x;
    const int lc = lenc[b];
    __shared__ float red[4];
    float s = (n < lc) ? scores[b * NNN + n] : -1e30f;
    float m = s;
    for (int o = 16; o; o >>= 1) m = fmaxf(m, __shfl_xor_sync(0xffffffffu, m, o));
    if ((n & 31) == 0) red[n >> 5] = m;
    __syncthreads();
    m = fmaxf(fmaxf(red[0], red[1]), fmaxf(red[2], red[3]));
    __syncthreads();
    float ev = (n < lc) ? expf(s - m) : 0.f;
    float sum = ev;
    for (int o = 16; o; o >>= 1) sum += __shfl_xor_sync(0xffffffffu, sum, o);
    if ((n & 31) == 0) red[n >> 5] = sum;
    __syncthreads();
    sum = red[0] + red[1] + red[2] + red[3];
    float pv = ev / sum;
    p[b * NNN + n] = pv;
    attout[b * NNN + n] = pv;
}

// ---------------- e[b][k] = sum_n csel[b][n][k] * p[b][n] --------------------
__global__ void __launch_bounds__(256) e_kernel(const float* __restrict__ csel,
                                                const float* __restrict__ p,
                                                float* __restrict__ e)
{
    const int b = blockIdx.x, k = threadIdx.x;
    __shared__ float ps[NNN];
    if (k < NNN) ps[k] = p[b * NNN + k];
    __syncthreads();
    float a0 = 0, a1 = 0;
    for (int n = 0; n < NNN; n += 2) {
        a0 += csel[(size_t)((b << 7) + n) * HHH + k] * ps[n];
        a1 += csel[(size_t)((b << 7) + n + 1) * HHH + k] * ps[n + 1];
    }
    e[b * HHH + k] = a0 + a1;
}

// ---------------- GRU gates via transposed weights ---------------------------
__global__ void __launch_bounds__(256) gates_kernel(
    const float* __restrict__ x1, int k1, const float* __restrict__ x2, int k2,
    const float* __restrict__ h, const float* __restrict__ wti,
    const float* __restrict__ wth, const float* __restrict__ bih,
    const float* __restrict__ bhh, float* __restrict__ gia, float* __restrict__ gha)
{
    const int b = blockIdx.x, rc = blockIdx.y, tid = threadIdx.x;
    const int r = rc * 256 + tid;
    __shared__ float xs[2304];
    __shared__ float hsm[HHH];
    for (int i = tid; i < k1; i += 256) xs[i] = x1[(size_t)b * k1 + i];
    for (int i = tid; i < k2; i += 256) xs[k1 + i] = x2[(size_t)b * k2 + i];
    hsm[tid] = h[b * HHH + tid];
    __syncthreads();
    const int K = k1 + k2;
    float a0 = 0, a1 = 0, a2 = 0, a3 = 0;
    int k = 0;
    for (; k + 4 <= K; k += 4) {
        a0 += xs[k]     * wti[(size_t)k * G3H + r];
        a1 += xs[k + 1] * wti[(size_t)(k + 1) * G3H + r];
        a2 += xs[k + 2] * wti[(size_t)(k + 2) * G3H + r];
        a3 += xs[k + 3] * wti[(size_t)(k + 3) * G3H + r];
    }
    for (; k < K; ++k) a0 += xs[k] * wti[(size_t)k * G3H + r];
    gia[b * G3H + r] = __ldg(bih + r) + (a0 + a1) + (a2 + a3);
    float c0 = 0, c1 = 0, c2 = 0, c3 = 0;
    for (int kk = 0; kk < HHH; kk += 4) {
        c0 += hsm[kk]     * wth[(size_t)kk * G3H + r];
        c1 += hsm[kk + 1] * wth[(size_t)(kk + 1) * G3H + r];
        c2 += hsm[kk + 2] * wth[(size_t)(kk + 2) * G3H + r];
        c3 += hsm[kk + 3] * wth[(size_t)(kk + 3) * G3H + r];
    }
    gha[b * G3H + r] = __ldg(bhh + r) + (c0 + c1) + (c2 + c3);
}

__global__ void __launch_bounds__(256) combine_kernel(
    const float* __restrict__ gia, const float* __restrict__ gha,
    const float* __restrict__ h, float* __restrict__ hout)
{
    const int b = blockIdx.x, k = threadIdx.x;
    float rg = 1.f / (1.f + expf(-(gia[b * G3H + k] + gha[b * G3H + k])));
    float zg = 1.f / (1.f + expf(-(gia[b * G3H + HHH + k] + gha[b * G3H + HHH + k])));
    float ng = tanhf(gia[b * G3H + 2 * HHH + k] + rg * gha[b * G3H + 2 * HHH + k]);
    hout[b * HHH + k] = (1.f - zg) * ng + zg * h[b * HHH + k];
}

// ---------------- logits via transposed out_w --------------------------------
__global__ void __launch_bounds__(256) logits_kernel(
    const float* __restrict__ hv, const float* __restrict__ owt,
    const float* __restrict__ ob, float* __restrict__ y)
{
    const int b = blockIdx.x, tid = threadIdx.x;
    const int o = blockIdx.y * 256 + tid;
    __shared__ float ms[HHH];
    ms[tid] = hv[b * HHH + tid];
    __syncthreads();
    if (o >= OOO) return;
    float a0 = 0, a1 = 0, a2 = 0, a3 = 0;
    for (int k = 0; k < HHH; k += 4) {
        a0 += ms[k]     * owt[(size_t)k * OOO + o];
        a1 += ms[k + 1] * owt[(size_t)(k + 1) * OOO + o];
        a2 += ms[k + 2] * owt[(size_t)(k + 2) * OOO + o];
        a3 += ms[k + 3] * owt[(size_t)(k + 3) * OOO + o];
    }
    y[(size_t)b * OOO + o] = __ldg(ob + o) + (a0 + a1) + (a2 + a3);
}

// ---------------- softmax over O=2000 ----------------------------------------
__global__ void __launch_bounds__(256) softmaxO_kernel(const float* __restrict__ yin,
                                                       float* __restrict__ yout)
{
    const int b = blockIdx.x, tid = threadIdx.x;
    __shared__ float red[8];
    float m = -1e30f;
    for (int o = tid; o < OOO; o += 256) m = fmaxf(m, yin[(size_t)b * OOO + o]);
    for (int o = 16; o; o >>= 1) m = fmaxf(m, __shfl_xor_sync(0xffffffffu, m, o));
    if ((tid & 31) == 0) red[tid >> 5] = m;
    __syncthreads();
    m = red[0];
    #pragma unroll
    for (int i = 1; i < 8; ++i) m = fmaxf(m, red[i]);
    __syncthreads();
    float sum = 0.f;
    for (int o = tid; o < OOO; o += 256) sum += expf(yin[(size_t)b * OOO + o] - m);
    for (int o = 16; o; o >>= 1) sum += __shfl_xor_sync(0xffffffffu, sum, o);
    if ((tid & 31) == 0) red[tid >> 5] = sum;
    __syncthreads();
    sum = 0.f;
    #pragma unroll
    for (int i = 0; i < 8; ++i) sum += red[i];
    float inv = 1.f / sum;
    for (int o = tid; o < OOO; o += 256)
        yout[(size_t)b * OOO + o] = expf(yin[(size_t)b * OOO + o] - m) * inv;
}

__global__ void copy_kernel(const float* __restrict__ s, float* __restrict__ d, int n)
{
    int i = blockIdx.x * 256 + threadIdx.x;
    if (i < n) d[i] = s[i];
}

// ------------------------------- launch --------------------------------------
extern "C" void kernel_launch(void* const* d_in, const int* in_sizes, int n_in,
                              void* d_out, int out_size)
{
    const float* c        = (const float*)d_in[0];
    const float* q        = (const float*)d_in[1];
    const float* i_state  = (const float*)d_in[2];
    const float* q_state  = (const float*)d_in[3];
    const float* in_w_ih  = (const float*)d_in[4];
    const float* in_w_hh  = (const float*)d_in[5];
    const float* in_b_ih  = (const float*)d_in[6];
    const float* in_b_hh  = (const float*)d_in[7];
    const float* qe_w_ih  = (const float*)d_in[8];
    const float* qe_w_hh  = (const float*)d_in[9];
    const float* qe_b_ih  = (const float*)d_in[10];
    const float* qe_b_hh  = (const float*)d_in[11];
    const float* att_weight = (const float*)d_in[12];
    const float* att_w1   = (const float*)d_in[13];
    const float* att_b1   = (const float*)d_in[14];
    const float* att_w2   = (const float*)d_in[15];
    const float* att_b2   = (const float*)d_in[16];
    const float* mem_w_ih = (const float*)d_in[17];
    const float* mem_w_hh = (const float*)d_in[18];
    const float* mem_b_ih = (const float*)d_in[19];
    const float* mem_b_hh = (const float*)d_in[20];
    const float* out_w    = (const float*)d_in[21];
    const float* out_b    = (const float*)d_in[22];
    const float* ans_w_ih = (const float*)d_in[23];
    const float* ans_w_hh = (const float*)d_in[24];
    const float* ans_b_ih = (const float*)d_in[25];
    const float* ans_b_hh = (const float*)d_in[26];
    const int*   c_index  = (const int*)d_in[27];
    const int*   len_c    = (const int*)d_in[28];
    float* out = (float*)d_out;

    float* gb = nullptr;
    cudaGetSymbolAddress((void**)&gb, g_buf);
    int* flags = nullptr;
    cudaGetSymbolAddress((void**)&flags, g_flag);

    float* GI   = gb + OFF_GI;
    float* GIQ  = gb + OFF_GIQ;
    float* HB   = gb + OFF_H;
    float* COUT = gb + OFF_COUT;
    float* QOUT = gb + OFF_QOUT;
    float* QH   = gb + OFF_QH;
    float* HTC  = gb + OFF_HTC;
    float* CSEL = gb + OFF_CSEL;
    float* CW   = gb + OFF_CW;
    float* DOTQ = gb + OFF_DOTQ;
    float* DOTM = gb + OFF_DOTM;
    float* T0   = gb + OFF_T0;
    float* M    = gb + OFF_M;
    float* SC   = gb + OFF_SC;
    float* P    = gb + OFF_P;
    float* E    = gb + OFF_E;
    float* MSQ  = gb + OFF_MSQ;
    float* Y    = gb + OFF_Y;
    float* W1T  = gb + OFF_W1T;
    float* BT   = gb + OFF_BT;
    float* WTAI = gb + OFF_WTAI;
    float* WTAH = gb + OFF_WTAH;
    float* WTMI = gb + OFF_WTMI;
    float* WTMH = gb + OFF_WTMH;
    float* OWT  = gb + OFF_OWT;
    float* GIA  = gb + OFF_GIA;
    float* GHA  = gb + OFF_GHA;

    // ---- weight transposes + w1t (independent prep) ----
    w1t_kernel<<<(FEAT * 128 + 255) / 256, 256>>>(att_w1, W1T);
    {
        dim3 blk(32, 8);
        transpose_kernel<<<dim3((2256 + 31) / 32, 24), blk>>>(ans_w_ih, WTAI, 768, 2256);
        transpose_kernel<<<dim3(8, 24), blk>>>(ans_w_hh, WTAH, 768, 256);
        transpose_kernel<<<dim3(8, 24), blk>>>(mem_w_ih, WTMI, 768, 256);
        transpose_kernel<<<dim3(8, 24), blk>>>(mem_w_hh, WTMH, 768, 256);
        transpose_kernel<<<dim3(8, (2000 + 31) / 32), blk>>>(out_w, OWT, 2000, 256);
    }

    // ---- context GRU ----
    gi_kernel<<<dim3(SSL, 4), 256>>>(c, in_w_ih, in_b_ih, GI, SSL);
    copy_kernel<<<(BB * HHH + 255) / 256, 256>>>(i_state, HB, BB * HHH);
    zeroflags_kernel<<<1, 128>>>(flags);
    rec_kernel<<<128, 128>>>(GI, in_w_hh, in_b_hh, SSL, HB, COUT, HTC, flags);

    // ---- query GRU ----
    gi_kernel<<<dim3(SQQ, 4), 256>>>(q, qe_w_ih, qe_b_ih, GIQ, SQQ);
    copy_kernel<<<(BB * HHH + 255) / 256, 256>>>(q_state, HB, BB * HHH);
    zeroflags_kernel<<<1, 128>>>(flags);
    rec_kernel<<<128, 128>>>(GIQ, qe_w_hh, qe_b_hh, SQQ, HB, QOUT, QH, flags);

    // ---- attention prep ----
    cwgather_kernel<<<BB * NNN / 16, 256>>>(COUT, c_index, att_weight, CSEL, CW);
    dot_kernel<<<BB * NNN, 64>>>(CW, QH, DOTQ);
    bterm_kernel<<<BB, 128>>>(QH, W1T, att_b1, 512, BT);
    attproj_kernel<true, false><<<BB * NNN / 16, 128>>>(
        CSEL, QH, nullptr, DOTQ, W1T, BT, 768, 1280, 1792, nullptr, nullptr, T0, nullptr);
    copy_kernel<<<(BB * HHH + 255) / 256, 256>>>(QH, M, BB * HHH);

    // ---- 3 memory hops ----
    for (int hop = 0; hop < 3; ++hop) {
        dot_kernel<<<BB * NNN, 64>>>(CW, M, DOTM);
        bterm_kernel<<<BB, 128>>>(M, W1T, nullptr, 256, BT);
        attproj_kernel<false, true><<<BB * NNN / 16, 128>>>(
            CSEL, M, T0, DOTM, W1T, BT, 1024, 1536, 1793, att_w2, att_b2, nullptr, SC);
        softmaxN_kernel<<<BB, NNN>>>(SC, len_c, P, out + BB * OOO + hop * BB * NNN);
        e_kernel<<<BB, HHH>>>(CSEL, P, E);
        gates_kernel<<<dim3(BB, 3), 256>>>(E, HHH, nullptr, 0, M,
                                           WTMI, WTMH, mem_b_ih, mem_b_hh, GIA, GHA);
        combine_kernel<<<BB, 256>>>(GIA, GHA, M, M);
    }

    // ---- answer loop ----
    copy_kernel<<<(BB * HHH + 255) / 256, 256>>>(M, MSQ, BB * HHH);
    for (int t = 0; t < 2; ++t) {
        logits_kernel<<<dim3(BB, 8), 256>>>(MSQ, OWT, out_b, Y);
        softmaxO_kernel<<<BB, 256>>>(Y, Y);
        gates_kernel<<<dim3(BB, 3), 256>>>(Y, OOO, QH, HHH, MSQ,
                                           WTAI, WTAH, ans_b_ih, ans_b_hh, GIA, GHA);
        combine_kernel<<<BB, 256>>>(GIA, GHA, MSQ, MSQ);
    }
    logits_kernel<<<dim3(BB, 8), 256>>>(MSQ, OWT, out_b, Y);
    softmaxO_kernel<<<BB, 256>>>(Y, out);
}

// round 11
// speedup vs baseline: 1.1740x; 1.1740x over previous
#include <cuda_runtime.h>
#include <math.h>

// Problem constants
#define BB   32
#define SSL  1024
#define SQQ  32
#define NNN  128
#define DINN 128
#define HHH  256
#define AAA  100
#define OOO  2000
#define G3H  768
#define FEAT 1794   // 7*H + 2

// ---------------- scratch offsets (floats) in one big device buffer ----------
#define OFF_GI    0UL          // 1024*768*32
#define OFF_GIQ   25165824UL   // 32*768*32
#define OFF_H     25952256UL   // 2*32*256 ping-pong h, [pp][b][k]
#define OFF_COUT  25968640UL   // 1024*256*32  [t][k][b]
#define OFF_QOUT  34357248UL   // 32*256*32
#define OFF_QH    34619392UL   // 32*256
#define OFF_HTC   34627584UL   // 32*256
#define OFF_CSEL  34635776UL   // 32*128*256
#define OFF_CW    35684352UL   // 32*128*256
#define OFF_DOTQ  36732928UL   // 4096
#define OFF_DOTM  36737024UL   // 4096
#define OFF_T0    36741120UL   // 4096*100
#define OFF_M     37150720UL   // 32*256
#define OFF_SC    37158912UL   // 4096
#define OFF_P     37163008UL   // 4096
#define OFF_E     37167104UL   // 32*256
#define OFF_MSQ   37175296UL   // 32*256
#define OFF_Y     37183488UL   // 32*2000
#define OFF_W1T   37247488UL   // 1794*128
#define OFF_BT    37477120UL   // 32*100
#define OFF_WTAI  37480320UL   // 2256*768
#define OFF_WTAH  39212928UL   // 256*768
#define OFF_WTMI  39409536UL   // 256*768
#define OFF_WTMH  39606144UL   // 256*768
#define OFF_OWT   39802752UL   // 256*2000
#define OFF_GIA   40314752UL   // 32*768
#define OFF_GHA   40339328UL   // 32*768
#define TOTALF    40363904UL

__device__ __align__(16) float g_buf[TOTALF];
__device__ __align__(64) int g_flag[128];   // per-block step counters (parallel stores)
__device__ __align__(64) int g_gen[16];     // aggregated generation (single word used)

// ---------------- packed f32x2 FMA helpers (sm_103a) -------------------------
__device__ __forceinline__ unsigned long long pk2(float x, float y) {
    unsigned long long r;
    asm("mov.b64 %0, {%1, %2};" : "=l"(r) : "f"(x), "f"(y));
    return r;
}
__device__ __forceinline__ float upsum(unsigned long long a, unsigned long long b) {
    float ax, ay, bx, by;
    asm("mov.b64 {%0, %1}, %2;" : "=f"(ax), "=f"(ay) : "l"(a));
    asm("mov.b64 {%0, %1}, %2;" : "=f"(bx), "=f"(by) : "l"(b));
    return (ax + ay) + (bx + by);
}
#define FMA2(acc, a, b) \
    asm("fma.rn.f32x2 %0, %1, %2, %0;" : "+l"(acc) : "l"(a), "l"(b))

// ---------------- zero flags + gen --------------------------------------------
__global__ void zeroflags_kernel(int* flags, int* gen)
{
    if (threadIdx.x < 128) flags[threadIdx.x] = 0;
    if (threadIdx.x == 128) gen[0] = 0;
}

// ---------------- gi = x @ w_ih^T + b_ih  ->  out[t][row][b] -----------------
// grid (S, 4): blockIdx.y selects a 192-row chunk. 4-row register blocking.
__global__ void __launch_bounds__(256) gi_kernel(
    const float* __restrict__ x, const float* __restrict__ w,
    const float* __restrict__ bias, float* __restrict__ out, int S)
{
    const int t = blockIdx.x;
    const int rbase = blockIdx.y * 192;
    __shared__ float4 xs4[32][33];   // [b][k4]
    for (int idx = threadIdx.x; idx < 1024; idx += 256) {
        int b = idx >> 5, k4 = idx & 31;
        xs4[b][k4] = __ldg(((const float4*)x) + ((size_t)b * S + t) * 32 + k4);
    }
    __syncthreads();
    const int b = threadIdx.x & 31, w0 = threadIdx.x >> 5;
    for (int r = rbase + w0 * 4; r < rbase + 192; r += 32) {
        const float4* wr0 = (const float4*)(w + (size_t)r * DINN);
        const float4* wr1 = wr0 + 32;
        const float4* wr2 = wr0 + 64;
        const float4* wr3 = wr0 + 96;
        float s[4][4];
        #pragma unroll
        for (int i = 0; i < 4; ++i)
            #pragma unroll
            for (int jj = 0; jj < 4; ++jj) s[i][jj] = 0.f;
        #pragma unroll
        for (int k4 = 0; k4 < 32; ++k4) {
            float4 xv = xs4[b][k4];
            float4 w0v = __ldg(wr0 + k4), w1v = __ldg(wr1 + k4);
            float4 w2v = __ldg(wr2 + k4), w3v = __ldg(wr3 + k4);
            s[0][0] += w0v.x * xv.x; s[0][1] += w0v.y * xv.y; s[0][2] += w0v.z * xv.z; s[0][3] += w0v.w * xv.w;
            s[1][0] += w1v.x * xv.x; s[1][1] += w1v.y * xv.y; s[1][2] += w1v.z * xv.z; s[1][3] += w1v.w * xv.w;
            s[2][0] += w2v.x * xv.x; s[2][1] += w2v.y * xv.y; s[2][2] += w2v.z * xv.z; s[2][3] += w2v.w * xv.w;
            s[3][0] += w3v.x * xv.x; s[3][1] += w3v.y * xv.y; s[3][2] += w3v.z * xv.z; s[3][3] += w3v.w * xv.w;
        }
        #pragma unroll
        for (int i = 0; i < 4; ++i)
            out[((size_t)t * G3H + r + i) * BB + b] =
                __ldg(bias + r + i) + (s[i][0] + s[i][1]) + (s[i][2] + s[i][3]);
    }
}

// ---------------- persistent GRU recurrence (129 blocks x 128 threads) -------
// Blocks 0..127 compute (block j owns h cols 2j, 2j+1 x 3 gates).
// Block 128 is a dedicated aggregator: it alone polls the 128 per-block flags
// (one coalesced 512B read per round), computes min, and publishes g_gen.
// Compute blocks poll ONLY the single gen word (one thread each) -> no
// contention on flag lines, no atomic serialization on arrival.
__global__ void __launch_bounds__(128, 1) rec_kernel(
    const float* __restrict__ gi, const float* __restrict__ whh,
    const float* __restrict__ bhh, int S,
    float* __restrict__ hbuf, float* __restrict__ cout,
    float* __restrict__ finalh, int* __restrict__ flags, int* __restrict__ gen)
{
    const int j = blockIdx.x;
    const int tid = threadIdx.x, wid = tid >> 5, lane = tid & 31;

    // ---- aggregator block ----
    if (j == 128) {
        if (tid < 32) {
            int published = 0;
            const int4* f4 = (const int4*)flags;
            while (published < S) {
                int4 v = __ldcg(f4 + lane);
                int m = min(min(v.x, v.y), min(v.z, v.w));
                #pragma unroll
                for (int o = 16; o; o >>= 1) m = min(m, __shfl_xor_sync(0xffffffffu, m, o));
                if (m > published) {
                    __threadfence();
                    if (lane == 0) *((volatile int*)gen) = m;
                    published = m;
                } else {
#if __CUDA_ARCH__ >= 700
                    __nanosleep(20);
#endif
                }
            }
        }
        return;
    }

    const int c0 = 2 * j;
    const int cb = wid & 1, kh = wid >> 1;

    __shared__ float4 hs4[32 * 65];          // [b][65 float4], stride 260 words (≡4 mod 32: conflict-free)
    __shared__ float  wss[6][HHH];           // [cb*3+g][k]
    __shared__ float  part[2][2][3][32];     // [cb][kh][g][b]
    __shared__ float  gis[6][32];            // [cb*3+g][b]
    __shared__ float  bsh[6];

    for (int i = tid; i < 6 * HHH; i += 128) {
        int d = i >> 8, k = i & 255;
        int cbb = d / 3, g = d % 3;
        wss[d][k] = whh[(size_t)(g * HHH + c0 + cbb) * HHH + k];
    }
    if (tid < 6) bsh[tid] = bhh[(tid % 3) * HHH + c0 + tid / 3];
    __syncthreads();

    int pp = 0;
    for (int t = 0; t < S; ++t) {
        // prefetch gi (independent of recurrence state) — long-scoreboard
        // latency absorbed while waiting on gen
        float g0 = __ldg(gi + ((size_t)t * G3H + (wid % 3) * HHH + c0 + wid / 3) * BB + lane);
        float g1 = 0.f;
        if (tid < 64) {
            int d1 = wid + 4;
            g1 = __ldg(gi + ((size_t)t * G3H + (d1 % 3) * HHH + c0 + d1 / 3) * BB + lane);
        }

        // acquire: single thread polls the single aggregated gen word
        if (t > 0) {
            if (tid == 0) {
                while (__ldcg(gen) < t) {
#if __CUDA_ARCH__ >= 700
                    __nanosleep(20);
#endif
                }
                __threadfence();
            }
            __syncthreads();
        }

        gis[wid][lane] = g0;
        if (tid < 64) gis[wid + 4][lane] = g1;

        // stage h[pp] (32 KB) as [b][k], L2-coherent
        const float4* src = (const float4*)(hbuf + pp * (BB * HHH));
        #pragma unroll
        for (int it = 0; it < 16; ++it) {
            int idx = tid + it * 128;
            hs4[(idx >> 6) * 65 + (idx & 63)] = __ldcg(src + idx);
        }
        __syncthreads();

        // register-blocked 3-gate dot with packed f32x2 FMAs:
        // same 4 partial accumulators per gate and same final sum order as the
        // scalar version -> bit-identical numerics.
        const float4* hp = &hs4[lane * 65 + kh * 32];
        const float4* wr = (const float4*)&wss[cb * 3 + 0][kh * 128];
        const float4* wz = (const float4*)&wss[cb * 3 + 1][kh * 128];
        const float4* wn = (const float4*)&wss[cb * 3 + 2][kh * 128];
        unsigned long long rA = 0, rB = 0, zA = 0, zB = 0, nA = 0, nB = 0;
        #pragma unroll
        for (int k4 = 0; k4 < 32; ++k4) {
            float4 hv = hp[k4];
            unsigned long long h0 = pk2(hv.x, hv.y), h1 = pk2(hv.z, hv.w);
            float4 wa = wr[k4];
            FMA2(rA, pk2(wa.x, wa.y), h0);
            FMA2(rB, pk2(wa.z, wa.w), h1);
            float4 wb = wz[k4];
            FMA2(zA, pk2(wb.x, wb.y), h0);
            FMA2(zB, pk2(wb.z, wb.w), h1);
            float4 wc = wn[k4];
            FMA2(nA, pk2(wc.x, wc.y), h0);
            FMA2(nB, pk2(wc.z, wc.w), h1);
        }
        part[cb][kh][0][lane] = upsum(rA, rB);
        part[cb][kh][1][lane] = upsum(zA, zB);
        part[cb][kh][2][lane] = upsum(nA, nB);
        __syncthreads();

        if (tid < 64) {
            int cc = tid >> 5, b = tid & 31, col = c0 + cc;
            float hr  = part[cc][0][0][b] + part[cc][1][0][b] + bsh[cc * 3 + 0];
            float hz  = part[cc][0][1][b] + part[cc][1][1][b] + bsh[cc * 3 + 1];
            float hn  = part[cc][0][2][b] + part[cc][1][2][b] + bsh[cc * 3 + 2];
            float rg = 1.f / (1.f + expf(-(gis[cc * 3 + 0][b] + hr)));
            float zg = 1.f / (1.f + expf(-(gis[cc * 3 + 1][b] + hz)));
            float ng = tanhf(gis[cc * 3 + 2][b] + rg * hn);
            float hold = ((const float*)hs4)[b * 260 + col];
            float hnew = (1.f - zg) * ng + zg * hold;
            hbuf[(pp ^ 1) * (BB * HHH) + b * HHH + col] = hnew;
            cout[((size_t)t * HHH + col) * BB + b] = hnew;   // [t][k][b] coalesced
            if (t == S - 1) finalh[b * HHH + col] = hnew;
        }
        __syncthreads();
        // release: per-block flag store (parallel across blocks, no atomics)
        if (tid == 0) { __threadfence(); ((volatile int*)flags)[j] = t + 1; }
        pp ^= 1;
    }
}

// ---------------- transpose src[R][K] -> dst[K][R] ---------------------------
__global__ void transpose_kernel(const float* __restrict__ src, float* __restrict__ dst,
                                 int R, int K)
{
    __shared__ float tile[32][33];
    int k0 = blockIdx.x * 32, r0 = blockIdx.y * 32;
    int lx = threadIdx.x, ly = threadIdx.y;   // 32 x 8
    for (int i = ly; i < 32; i += 8) {
        int r = r0 + i, k = k0 + lx;
        tile[i][lx] = (r < R && k < K) ? src[(size_t)r * K + k] : 0.f;
    }
    __syncthreads();
    for (int i = ly; i < 32; i += 8) {
        int k = k0 + i, r = r0 + lx;
        if (k < K && r < R) dst[(size_t)k * R + r] = tile[lx][i];
    }
}

// ---------------- transpose att_w1 -> w1t[f][a] padded to 128 ----------------
__global__ void w1t_kernel(const float* __restrict__ w1, float* __restrict__ w1t)
{
    int idx = blockIdx.x * 256 + threadIdx.x;
    if (idx >= FEAT * 128) return;
    int f = idx >> 7, a = idx & 127;
    w1t[idx] = (a < AAA) ? w1[a * FEAT + f] : 0.f;
}

// ---------------- gather c_sel (from [t][k][b]) + cw = c_sel @ att_weight ----
__global__ void __launch_bounds__(256) cwgather_kernel(
    const float* __restrict__ cout, const int* __restrict__ cindex,
    const float* __restrict__ attw, float* __restrict__ csel, float* __restrict__ cw)
{
    const int r0 = blockIdx.x * 16;
    const int b  = r0 >> 7;
    const int tid = threadIdx.x;
    __shared__ float cs[16][HHH];
    __shared__ int ti[16];
    if (tid < 16) ti[tid] = cindex[b * NNN + ((r0 + tid) & 127)];
    __syncthreads();
    for (int idx = tid; idx < 16 * HHH; idx += 256) {
        int r = idx >> 8, k = idx & 255;
        float v = cout[((size_t)ti[r] * HHH + k) * BB + b];
        cs[r][k] = v;
        csel[(size_t)(r0 + r) * HHH + k] = v;
    }
    __syncthreads();
    float acc[16];
    #pragma unroll
    for (int r = 0; r < 16; ++r) acc[r] = 0.f;
    const int jcol = tid;
    for (int k = 0; k < HHH; ++k) {
        float wk = __ldg(attw + k * HHH + jcol);
        #pragma unroll
        for (int r = 0; r < 16; ++r) acc[r] += cs[r][k] * wk;
    }
    #pragma unroll
    for (int r = 0; r < 16; ++r) cw[(size_t)(r0 + r) * HHH + jcol] = acc[r];
}

// ---------------- per-row dot with per-b vector ------------------------------
__global__ void dot_kernel(const float* __restrict__ mat, const float* __restrict__ vec,
                           float* __restrict__ out)
{
    const int row = blockIdx.x;
    const int b = row >> 7;
    const int tid = threadIdx.x;   // 64
    const float4* mr = (const float4*)(mat + (size_t)row * HHH);
    const float4* vr = (const float4*)(vec + b * HHH);
    float4 a = mr[tid], v = vr[tid];
    float s = a.x * v.x + a.y * v.y + a.z * v.z + a.w * v.w;
    for (int o = 16; o; o >>= 1) s += __shfl_xor_sync(0xffffffffu, s, o);
    __shared__ float sm[2];
    if ((tid & 31) == 0) sm[tid >> 5] = s;
    __syncthreads();
    if (tid == 0) out[row] = sm[0] + sm[1];
}

// ---------------- bterm[b][a] = (b1?) + v[b] . w1t_cols(off..off+256) --------
__global__ void bterm_kernel(const float* __restrict__ v, const float* __restrict__ w1t,
                             const float* __restrict__ b1, int off, float* __restrict__ out)
{
    const int b = blockIdx.x, a = threadIdx.x;   // 128 threads
    __shared__ float vs[HHH];
    for (int i = a; i < HHH; i += 128) vs[i] = v[b * HHH + i];
    __syncthreads();
    float a0 = 0, a1 = 0, a2 = 0, a3 = 0;
    for (int k = 0; k < HHH; k += 4) {
        a0 += vs[k]     * w1t[(off + k) * 128 + a];
        a1 += vs[k + 1] * w1t[(off + k + 1) * 128 + a];
        a2 += vs[k + 2] * w1t[(off + k + 2) * 128 + a];
        a3 += vs[k + 3] * w1t[(off + k + 3) * 128 + a];
    }
    if (a < AAA) out[b * AAA + a] = (b1 ? __ldg(b1 + a) : 0.f) + (a0 + a1) + (a2 + a3);
}

// ---------------- attention projection (T0 precompute or hop+score) ----------
template <bool USEC, bool SCORE>
__global__ void __launch_bounds__(128) attproj_kernel(
    const float* __restrict__ csel, const float* __restrict__ vvec,
    const float* __restrict__ base, const float* __restrict__ dotv,
    const float* __restrict__ w1t, const float* __restrict__ bterm,
    int o2, int o3, int dotcol,
    const float* __restrict__ w2, const float* __restrict__ b2,
    float* __restrict__ outT0, float* __restrict__ outScores)
{
    const int r0 = blockIdx.x * 16;
    const int b  = r0 >> 7;
    const int tid = threadIdx.x;
    __shared__ float cs[16][HHH];
    __shared__ float vs[HHH];
    __shared__ float tvs[16][128];
    for (int idx = tid; idx < 16 * HHH; idx += 128)
        cs[idx >> 8][idx & 255] = csel[(size_t)(r0 + (idx >> 8)) * HHH + (idx & 255)];
    for (int idx = tid; idx < HHH; idx += 128) vs[idx] = vvec[b * HHH + idx];
    __syncthreads();

    const int a = tid;
    const bool va = a < AAA;
    float bt = va ? bterm[b * AAA + a] : 0.f;
    float wd = w1t[dotcol * 128 + a];
    float acc[16];
    #pragma unroll
    for (int r = 0; r < 16; ++r) {
        float v0 = bt + dotv[r0 + r] * wd;
        if (SCORE && va) v0 += base[(size_t)(r0 + r) * AAA + a];
        acc[r] = v0;
    }
    for (int k = 0; k < HHH; ++k) {
        float f1 = USEC ? w1t[k * 128 + a] : 0.f;
        float f2 = w1t[(o2 + k) * 128 + a];
        float f3 = w1t[(o3 + k) * 128 + a];
        float vk = vs[k];
        #pragma unroll
        for (int r = 0; r < 16; ++r) {
            float c = cs[r][k];
            acc[r] += (c * vk) * f2 + fabsf(c - vk) * f3;
            if (USEC) acc[r] += c * f1;
        }
    }
    if (!SCORE) {
        if (va) {
            #pragma unroll
            for (int r = 0; r < 16; ++r) outT0[(size_t)(r0 + r) * AAA + a] = acc[r];
        }
    } else {
        float w2a = va ? __ldg(w2 + a) : 0.f;
        #pragma unroll
        for (int r = 0; r < 16; ++r) tvs[r][a] = va ? tanhf(acc[r]) * w2a : 0.f;
        __syncthreads();
        int wq = tid >> 5, ln = tid & 31;
        #pragma unroll
        for (int rr = 0; rr < 4; ++rr) {
            int row = wq * 4 + rr;
            float s = tvs[row][ln] + tvs[row][ln + 32] + tvs[row][ln + 64] + tvs[row][ln + 96];
            for (int o = 16; o; o >>= 1) s += __shfl_xor_sync(0xffffffffu, s, o);
            if (ln == 0) outScores[r0 + row] = s + __ldg(b2);
        }
    }
}

// ---------------- masked softmax over N=128 ----------------------------------
__global__ void softmaxN_kernel(const float* __restrict__ scores, const int* __restrict__ lenc,
                                float* __restrict__ p, float* __restrict__ attout)
{
    const int b = blockIdx.x, n = threadIdx.x;
    const int lc = lenc[b];
    __shared__ float red[4];
    float s = (n < lc) ? scores[b * NNN + n] : -1e30f;
    float m = s;
    for (int o = 16; o; o >>= 1) m = fmaxf(m, __shfl_xor_sync(0xffffffffu, m, o));
    if ((n & 31) == 0) red[n >> 5] = m;
    __syncthreads();
    m = fmaxf(fmaxf(red[0], red[1]), fmaxf(red[2], red[3]));
    __syncthreads();
    float ev = (n < lc) ? expf(s - m) : 0.f;
    float sum = ev;
    for (int o = 16; o; o >>= 1) sum += __shfl_xor_sync(0xffffffffu, sum, o);
    if ((n & 31) == 0) red[n >> 5] = sum;
    __syncthreads();
    sum = red[0] + red[1] + red[2] + red[3];
    float pv = ev / sum;
    p[b * NNN + n] = pv;
    attout[b * NNN + n] = pv;
}

// ---------------- e[b][k] = sum_n csel[b][n][k] * p[b][n] --------------------
__global__ void __launch_bounds__(256) e_kernel(const float* __restrict__ csel,
                                                const float* __restrict__ p,
                                                float* __restrict__ e)
{
    const int b = blockIdx.x, k = threadIdx.x;
    __shared__ float ps[NNN];
    if (k < NNN) ps[k] = p[b * NNN + k];
    __syncthreads();
    float a0 = 0, a1 = 0;
    for (int n = 0; n < NNN; n += 2) {
        a0 += csel[(size_t)((b << 7) + n) * HHH + k] * ps[n];
        a1 += csel[(size_t)((b << 7) + n + 1) * HHH + k] * ps[n + 1];
    }
    e[b * HHH + k] = a0 + a1;
}

// ---------------- GRU gates via transposed weights ---------------------------
__global__ void __launch_bounds__(256) gates_kernel(
    const float* __restrict__ x1, int k1, const float* __restrict__ x2, int k2,
    const float* __restrict__ h, const float* __restrict__ wti,
    const float* __restrict__ wth, const float* __restrict__ bih,
    const float* __restrict__ bhh, float* __restrict__ gia, float* __restrict__ gha)
{
    const int b = blockIdx.x, rc = blockIdx.y, tid = threadIdx.x;
    const int r = rc * 256 + tid;
    __shared__ float xs[2304];
    __shared__ float hsm[HHH];
    for (int i = tid; i < k1; i += 256) xs[i] = x1[(size_t)b * k1 + i];
    for (int i = tid; i < k2; i += 256) xs[k1 + i] = x2[(size_t)b * k2 + i];
    hsm[tid] = h[b * HHH + tid];
    __syncthreads();
    const int K = k1 + k2;
    float a0 = 0, a1 = 0, a2 = 0, a3 = 0;
    int k = 0;
    for (; k + 4 <= K; k += 4) {
        a0 += xs[k]     * wti[(size_t)k * G3H + r];
        a1 += xs[k + 1] * wti[(size_t)(k + 1) * G3H + r];
        a2 += xs[k + 2] * wti[(size_t)(k + 2) * G3H + r];
        a3 += xs[k + 3] * wti[(size_t)(k + 3) * G3H + r];
    }
    for (; k < K; ++k) a0 += xs[k] * wti[(size_t)k * G3H + r];
    gia[b * G3H + r] = __ldg(bih + r) + (a0 + a1) + (a2 + a3);
    float c0 = 0, c1 = 0, c2 = 0, c3 = 0;
    for (int kk = 0; kk < HHH; kk += 4) {
        c0 += hsm[kk]     * wth[(size_t)kk * G3H + r];
        c1 += hsm[kk + 1] * wth[(size_t)(kk + 1) * G3H + r];
        c2 += hsm[kk + 2] * wth[(size_t)(kk + 2) * G3H + r];
        c3 += hsm[kk + 3] * wth[(size_t)(kk + 3) * G3H + r];
    }
    gha[b * G3H + r] = __ldg(bhh + r) + (c0 + c1) + (c2 + c3);
}

__global__ void __launch_bounds__(256) combine_kernel(
    const float* __restrict__ gia, const float* __restrict__ gha,
    const float* __restrict__ h, float* __restrict__ hout)
{
    const int b = blockIdx.x, k = threadIdx.x;
    float rg = 1.f / (1.f + expf(-(gia[b * G3H + k] + gha[b * G3H + k])));
    float zg = 1.f / (1.f + expf(-(gia[b * G3H + HHH + k] + gha[b * G3H + HHH + k])));
    float ng = tanhf(gia[b * G3H + 2 * HHH + k] + rg * gha[b * G3H + 2 * HHH + k]);
    hout[b * HHH + k] = (1.f - zg) * ng + zg * h[b * HHH + k];
}

// ---------------- logits via transposed out_w --------------------------------
__global__ void __launch_bounds__(256) logits_kernel(
    const float* __restrict__ hv, const float* __restrict__ owt,
    const float* __restrict__ ob, float* __restrict__ y)
{
    const int b = blockIdx.x, tid = threadIdx.x;
    const int o = blockIdx.y * 256 + tid;
    __shared__ float ms[HHH];
    ms[tid] = hv[b * HHH + tid];
    __syncthreads();
    if (o >= OOO) return;
    float a0 = 0, a1 = 0, a2 = 0, a3 = 0;
    for (int k = 0; k < HHH; k += 4) {
        a0 += ms[k]     * owt[(size_t)k * OOO + o];
        a1 += ms[k + 1] * owt[(size_t)(k + 1) * OOO + o];
        a2 += ms[k + 2] * owt[(size_t)(k + 2) * OOO + o];
        a3 += ms[k + 3] * owt[(size_t)(k + 3) * OOO + o];
    }
    y[(size_t)b * OOO + o] = __ldg(ob + o) + (a0 + a1) + (a2 + a3);
}

// ---------------- softmax over O=2000 ----------------------------------------
__global__ void __launch_bounds__(256) softmaxO_kernel(const float* __restrict__ yin,
                                                       float* __restrict__ yout)
{
    const int b = blockIdx.x, tid = threadIdx.x;
    __shared__ float red[8];
    float m = -1e30f;
    for (int o = tid; o < OOO; o += 256) m = fmaxf(m, yin[(size_t)b * OOO + o]);
    for (int o = 16; o; o >>= 1) m = fmaxf(m, __shfl_xor_sync(0xffffffffu, m, o));
    if ((tid & 31) == 0) red[tid >> 5] = m;
    __syncthreads();
    m = red[0];
    #pragma unroll
    for (int i = 1; i < 8; ++i) m = fmaxf(m, red[i]);
    __syncthreads();
    float sum = 0.f;
    for (int o = tid; o < OOO; o += 256) sum += expf(yin[(size_t)b * OOO + o] - m);
    for (int o = 16; o; o >>= 1) sum += __shfl_xor_sync(0xffffffffu, sum, o);
    if ((tid & 31) == 0) red[tid >> 5] = sum;
    __syncthreads();
    sum = 0.f;
    #pragma unroll
    for (int i = 0; i < 8; ++i) sum += red[i];
    float inv = 1.f / sum;
    for (int o = tid; o < OOO; o += 256)
        yout[(size_t)b * OOO + o] = expf(yin[(size_t)b * OOO + o] - m) * inv;
}

__global__ void copy_kernel(const float* __restrict__ s, float* __restrict__ d, int n)
{
    int i = blockIdx.x * 256 + threadIdx.x;
    if (i < n) d[i] = s[i];
}

// ------------------------------- launch --------------------------------------
extern "C" void kernel_launch(void* const* d_in, const int* in_sizes, int n_in,
                              void* d_out, int out_size)
{
    const float* c        = (const float*)d_in[0];
    const float* q        = (const float*)d_in[1];
    const float* i_state  = (const float*)d_in[2];
    const float* q_state  = (const float*)d_in[3];
    const float* in_w_ih  = (const float*)d_in[4];
    const float* in_w_hh  = (const float*)d_in[5];
    const float* in_b_ih  = (const float*)d_in[6];
    const float* in_b_hh  = (const float*)d_in[7];
    const float* qe_w_ih  = (const float*)d_in[8];
    const float* qe_w_hh  = (const float*)d_in[9];
    const float* qe_b_ih  = (const float*)d_in[10];
    const float* qe_b_hh  = (const float*)d_in[11];
    const float* att_weight = (const float*)d_in[12];
    const float* att_w1   = (const float*)d_in[13];
    const float* att_b1   = (const float*)d_in[14];
    const float* att_w2   = (const float*)d_in[15];
    const float* att_b2   = (const float*)d_in[16];
    const float* mem_w_ih = (const float*)d_in[17];
    const float* mem_w_hh = (const float*)d_in[18];
    const float* mem_b_ih = (const float*)d_in[19];
    const float* mem_b_hh = (const float*)d_in[20];
    const float* out_w    = (const float*)d_in[21];
    const float* out_b    = (const float*)d_in[22];
    const float* ans_w_ih = (const float*)d_in[23];
    const float* ans_w_hh = (const float*)d_in[24];
    const float* ans_b_ih = (const float*)d_in[25];
    const float* ans_b_hh = (const float*)d_in[26];
    const int*   c_index  = (const int*)d_in[27];
    const int*   len_c    = (const int*)d_in[28];
    float* out = (float*)d_out;

    float* gb = nullptr;
    cudaGetSymbolAddress((void**)&gb, g_buf);
    int* flags = nullptr;
    cudaGetSymbolAddress((void**)&flags, g_flag);
    int* gen = nullptr;
    cudaGetSymbolAddress((void**)&gen, g_gen);

    float* GI   = gb + OFF_GI;
    float* GIQ  = gb + OFF_GIQ;
    float* HB   = gb + OFF_H;
    float* COUT = gb + OFF_COUT;
    float* QOUT = gb + OFF_QOUT;
    float* QH   = gb + OFF_QH;
    float* HTC  = gb + OFF_HTC;
    float* CSEL = gb + OFF_CSEL;
    float* CW   = gb + OFF_CW;
    float* DOTQ = gb + OFF_DOTQ;
    float* DOTM = gb + OFF_DOTM;
    float* T0   = gb + OFF_T0;
    float* M    = gb + OFF_M;
    float* SC   = gb + OFF_SC;
    float* P    = gb + OFF_P;
    float* E    = gb + OFF_E;
    float* MSQ  = gb + OFF_MSQ;
    float* Y    = gb + OFF_Y;
    float* W1T  = gb + OFF_W1T;
    float* BT   = gb + OFF_BT;
    float* WTAI = gb + OFF_WTAI;
    float* WTAH = gb + OFF_WTAH;
    float* WTMI = gb + OFF_WTMI;
    float* WTMH = gb + OFF_WTMH;
    float* OWT  = gb + OFF_OWT;
    float* GIA  = gb + OFF_GIA;
    float* GHA  = gb + OFF_GHA;

    // ---- weight transposes + w1t (independent prep) ----
    w1t_kernel<<<(FEAT * 128 + 255) / 256, 256>>>(att_w1, W1T);
    {
        dim3 blk(32, 8);
        transpose_kernel<<<dim3((2256 + 31) / 32, 24), blk>>>(ans_w_ih, WTAI, 768, 2256);
        transpose_kernel<<<dim3(8, 24), blk>>>(ans_w_hh, WTAH, 768, 256);
        transpose_kernel<<<dim3(8, 24), blk>>>(mem_w_ih, WTMI, 768, 256);
        transpose_kernel<<<dim3(8, 24), blk>>>(mem_w_hh, WTMH, 768, 256);
        transpose_kernel<<<dim3(8, (2000 + 31) / 32), blk>>>(out_w, OWT, 2000, 256);
    }

    // ---- context GRU ----
    gi_kernel<<<dim3(SSL, 4), 256>>>(c, in_w_ih, in_b_ih, GI, SSL);
    copy_kernel<<<(BB * HHH + 255) / 256, 256>>>(i_state, HB, BB * HHH);
    zeroflags_kernel<<<1, 160>>>(flags, gen);
    rec_kernel<<<129, 128>>>(GI, in_w_hh, in_b_hh, SSL, HB, COUT, HTC, flags, gen);

    // ---- query GRU ----
    gi_kernel<<<dim3(SQQ, 4), 256>>>(q, qe_w_ih, qe_b_ih, GIQ, SQQ);
    copy_kernel<<<(BB * HHH + 255) / 256, 256>>>(q_state, HB, BB * HHH);
    zeroflags_kernel<<<1, 160>>>(flags, gen);
    rec_kernel<<<129, 128>>>(GIQ, qe_w_hh, qe_b_hh, SQQ, HB, QOUT, QH, flags, gen);

    // ---- attention prep ----
    cwgather_kernel<<<BB * NNN / 16, 256>>>(COUT, c_index, att_weight, CSEL, CW);
    dot_kernel<<<BB * NNN, 64>>>(CW, QH, DOTQ);
    bterm_kernel<<<BB, 128>>>(QH, W1T, att_b1, 512, BT);
    attproj_kernel<true, false><<<BB * NNN / 16, 128>>>(
        CSEL, QH, nullptr, DOTQ, W1T, BT, 768, 1280, 1792, nullptr, nullptr, T0, nullptr);
    copy_kernel<<<(BB * HHH + 255) / 256, 256>>>(QH, M, BB * HHH);

    // ---- 3 memory hops ----
    for (int hop = 0; hop < 3; ++hop) {
        dot_kernel<<<BB * NNN, 64>>>(CW, M, DOTM);
        bterm_kernel<<<BB, 128>>>(M, W1T, nullptr, 256, BT);
        attproj_kernel<false, true><<<BB * NNN / 16, 128>>>(
            CSEL, M, T0, DOTM, W1T, BT, 1024, 1536, 1793, att_w2, att_b2, nullptr, SC);
        softmaxN_kernel<<<BB, NNN>>>(SC, len_c, P, out + BB * OOO + hop * BB * NNN);
        e_kernel<<<BB, HHH>>>(CSEL, P, E);
        gates_kernel<<<dim3(BB, 3), 256>>>(E, HHH, nullptr, 0, M,
                                           WTMI, WTMH, mem_b_ih, mem_b_hh, GIA, GHA);
        combine_kernel<<<BB, 256>>>(GIA, GHA, M, M);
    }

    // ---- answer loop ----
    copy_kernel<<<(BB * HHH + 255) / 256, 256>>>(M, MSQ, BB * HHH);
    for (int t = 0; t < 2; ++t) {
        logits_kernel<<<dim3(BB, 8), 256>>>(MSQ, OWT, out_b, Y);
        softmaxO_kernel<<<BB, 256>>>(Y, Y);
        gates_kernel<<<dim3(BB, 3), 256>>>(Y, OOO, QH, HHH, MSQ,
                                           WTAI, WTAH, ans_b_ih, ans_b_hh, GIA, GHA);
        combine_kernel<<<BB, 256>>>(GIA, GHA, MSQ, MSQ);
    }
    logits_kernel<<<dim3(BB, 8), 256>>>(MSQ, OWT, out_b, Y);
    softmaxO_kernel<<<BB, 256>>>(Y, out);
}

// round 12
// speedup vs baseline: 1.1818x; 1.0066x over previous
#include <cuda_runtime.h>
#include <math.h>

// Problem constants
#define BB   32
#define SSL  1024
#define SQQ  32
#define NNN  128
#define DINN 128
#define HHH  256
#define AAA  100
#define OOO  2000
#define G3H  768
#define FEAT 1794   // 7*H + 2

// ---------------- scratch offsets (floats) in one big device buffer ----------
#define OFF_GI    0UL          // 1024*768*32
#define OFF_GIQ   25165824UL   // 32*768*32
#define OFF_H     25952256UL   // 2*32*256 ping-pong h, [pp][b][k]
#define OFF_COUT  25968640UL   // 1024*256*32  [t][k][b]
#define OFF_QOUT  34357248UL   // 32*256*32
#define OFF_QH    34619392UL   // 32*256
#define OFF_HTC   34627584UL   // 32*256
#define OFF_CSEL  34635776UL   // 32*128*256
#define OFF_CW    35684352UL   // 32*128*256
#define OFF_DOTQ  36732928UL   // 4096
#define OFF_DOTM  36737024UL   // 4096
#define OFF_T0    36741120UL   // 4096*100
#define OFF_M     37150720UL   // 32*256
#define OFF_SC    37158912UL   // 4096
#define OFF_P     37163008UL   // 4096
#define OFF_E     37167104UL   // 32*256
#define OFF_MSQ   37175296UL   // 32*256
#define OFF_Y     37183488UL   // 32*2000
#define OFF_W1T   37247488UL   // 1794*128
#define OFF_BT    37477120UL   // 32*100
#define OFF_WTAI  37480320UL   // 2256*768
#define OFF_WTAH  39212928UL   // 256*768
#define OFF_WTMI  39409536UL   // 256*768
#define OFF_WTMH  39606144UL   // 256*768
#define OFF_OWT   39802752UL   // 256*2000
#define OFF_GIA   40314752UL   // 32*768
#define OFF_GHA   40339328UL   // 32*768
#define TOTALF    40363904UL

__device__ __align__(16) float g_buf[TOTALF];
__device__ __align__(64) int g_flag[128];   // per-block step counters (parallel stores)
__device__ __align__(64) int g_gen[16];     // aggregated generation (single word used)

// ---------------- packed f32x2 FMA helpers (sm_103a) -------------------------
__device__ __forceinline__ unsigned long long pk2(float x, float y) {
    unsigned long long r;
    asm("mov.b64 %0, {%1, %2};" : "=l"(r) : "f"(x), "f"(y));
    return r;
}
__device__ __forceinline__ float upsum(unsigned long long a, unsigned long long b) {
    float ax, ay, bx, by;
    asm("mov.b64 {%0, %1}, %2;" : "=f"(ax), "=f"(ay) : "l"(a));
    asm("mov.b64 {%0, %1}, %2;" : "=f"(bx), "=f"(by) : "l"(b));
    return (ax + ay) + (bx + by);
}
#define FMA2(acc, a, b) \
    asm("fma.rn.f32x2 %0, %1, %2, %0;" : "+l"(acc) : "l"(a), "l"(b))

// ---------------- zero flags + gen --------------------------------------------
__global__ void zeroflags_kernel(int* flags, int* gen)
{
    if (threadIdx.x < 128) flags[threadIdx.x] = 0;
    if (threadIdx.x == 128) gen[0] = 0;
}

// ---------------- gi = x @ w_ih^T + b_ih  ->  out[t][row][b] -----------------
// grid (S, 4): blockIdx.y selects a 192-row chunk. 4-row register blocking.
__global__ void __launch_bounds__(256) gi_kernel(
    const float* __restrict__ x, const float* __restrict__ w,
    const float* __restrict__ bias, float* __restrict__ out, int S)
{
    const int t = blockIdx.x;
    const int rbase = blockIdx.y * 192;
    __shared__ float4 xs4[32][33];   // [b][k4]
    for (int idx = threadIdx.x; idx < 1024; idx += 256) {
        int b = idx >> 5, k4 = idx & 31;
        xs4[b][k4] = __ldg(((const float4*)x) + ((size_t)b * S + t) * 32 + k4);
    }
    __syncthreads();
    const int b = threadIdx.x & 31, w0 = threadIdx.x >> 5;
    for (int r = rbase + w0 * 4; r < rbase + 192; r += 32) {
        const float4* wr0 = (const float4*)(w + (size_t)r * DINN);
        const float4* wr1 = wr0 + 32;
        const float4* wr2 = wr0 + 64;
        const float4* wr3 = wr0 + 96;
        float s[4][4];
        #pragma unroll
        for (int i = 0; i < 4; ++i)
            #pragma unroll
            for (int jj = 0; jj < 4; ++jj) s[i][jj] = 0.f;
        #pragma unroll
        for (int k4 = 0; k4 < 32; ++k4) {
            float4 xv = xs4[b][k4];
            float4 w0v = __ldg(wr0 + k4), w1v = __ldg(wr1 + k4);
            float4 w2v = __ldg(wr2 + k4), w3v = __ldg(wr3 + k4);
            s[0][0] += w0v.x * xv.x; s[0][1] += w0v.y * xv.y; s[0][2] += w0v.z * xv.z; s[0][3] += w0v.w * xv.w;
            s[1][0] += w1v.x * xv.x; s[1][1] += w1v.y * xv.y; s[1][2] += w1v.z * xv.z; s[1][3] += w1v.w * xv.w;
            s[2][0] += w2v.x * xv.x; s[2][1] += w2v.y * xv.y; s[2][2] += w2v.z * xv.z; s[2][3] += w2v.w * xv.w;
            s[3][0] += w3v.x * xv.x; s[3][1] += w3v.y * xv.y; s[3][2] += w3v.z * xv.z; s[3][3] += w3v.w * xv.w;
        }
        #pragma unroll
        for (int i = 0; i < 4; ++i)
            out[((size_t)t * G3H + r + i) * BB + b] =
                __ldg(bias + r + i) + (s[i][0] + s[i][1]) + (s[i][2] + s[i][3]);
    }
}

// ---------------- persistent GRU recurrence (129 blocks x 128 threads) -------
// Blocks 0..127 compute (block j owns h cols 2j, 2j+1 x 3 gates).
// Block 128 is a dedicated aggregator: it alone polls the 128 per-block flags
// (one coalesced 512B read per round), computes min, and publishes g_gen.
// Compute blocks poll ONLY the single gen word (one thread each) -> no
// contention on flag lines, no atomic serialization on arrival.
__global__ void __launch_bounds__(128, 1) rec_kernel(
    const float* __restrict__ gi, const float* __restrict__ whh,
    const float* __restrict__ bhh, int S,
    float* __restrict__ hbuf, float* __restrict__ cout,
    float* __restrict__ finalh, int* __restrict__ flags, int* __restrict__ gen)
{
    const int j = blockIdx.x;
    const int tid = threadIdx.x, wid = tid >> 5, lane = tid & 31;

    // ---- aggregator block ----
    if (j == 128) {
        if (tid < 32) {
            int published = 0;
            const int4* f4 = (const int4*)flags;
            while (published < S) {
                int4 v = __ldcg(f4 + lane);
                int m = min(min(v.x, v.y), min(v.z, v.w));
                #pragma unroll
                for (int o = 16; o; o >>= 1) m = min(m, __shfl_xor_sync(0xffffffffu, m, o));
                if (m > published) {
                    __threadfence();
                    if (lane == 0) *((volatile int*)gen) = m;
                    published = m;
                } else {
#if __CUDA_ARCH__ >= 700
                    __nanosleep(20);
#endif
                }
            }
        }
        return;
    }

    const int c0 = 2 * j;
    const int cb = wid & 1, kh = wid >> 1;

    __shared__ float4 hs4[32 * 65];          // [b][65 float4], stride 260 words (≡4 mod 32: conflict-free)
    __shared__ float  wss[6][HHH];           // [cb*3+g][k]
    __shared__ float  part[2][2][3][32];     // [cb][kh][g][b]
    __shared__ float  gis[6][32];            // [cb*3+g][b]
    __shared__ float  bsh[6];

    for (int i = tid; i < 6 * HHH; i += 128) {
        int d = i >> 8, k = i & 255;
        int cbb = d / 3, g = d % 3;
        wss[d][k] = whh[(size_t)(g * HHH + c0 + cbb) * HHH + k];
    }
    if (tid < 6) bsh[tid] = bhh[(tid % 3) * HHH + c0 + tid / 3];
    __syncthreads();

    int pp = 0;
    for (int t = 0; t < S; ++t) {
        // prefetch gi (independent of recurrence state) — long-scoreboard
        // latency absorbed while waiting on gen
        float g0 = __ldg(gi + ((size_t)t * G3H + (wid % 3) * HHH + c0 + wid / 3) * BB + lane);
        float g1 = 0.f;
        if (tid < 64) {
            int d1 = wid + 4;
            g1 = __ldg(gi + ((size_t)t * G3H + (d1 % 3) * HHH + c0 + d1 / 3) * BB + lane);
        }

        // acquire: single thread polls the single aggregated gen word
        if (t > 0) {
            if (tid == 0) {
                while (__ldcg(gen) < t) {
#if __CUDA_ARCH__ >= 700
                    __nanosleep(20);
#endif
                }
                __threadfence();
            }
            __syncthreads();
        }

        gis[wid][lane] = g0;
        if (tid < 64) gis[wid + 4][lane] = g1;

        // stage h[pp] (32 KB) as [b][k], L2-coherent
        const float4* src = (const float4*)(hbuf + pp * (BB * HHH));
        #pragma unroll
        for (int it = 0; it < 16; ++it) {
            int idx = tid + it * 128;
            hs4[(idx >> 6) * 65 + (idx & 63)] = __ldcg(src + idx);
        }
        __syncthreads();

        // register-blocked 3-gate dot with packed f32x2 FMAs:
        // same 4 partial accumulators per gate and same final sum order as the
        // scalar version -> bit-identical numerics.
        const float4* hp = &hs4[lane * 65 + kh * 32];
        const float4* wr = (const float4*)&wss[cb * 3 + 0][kh * 128];
        const float4* wz = (const float4*)&wss[cb * 3 + 1][kh * 128];
        const float4* wn = (const float4*)&wss[cb * 3 + 2][kh * 128];
        unsigned long long rA = 0, rB = 0, zA = 0, zB = 0, nA = 0, nB = 0;
        #pragma unroll
        for (int k4 = 0; k4 < 32; ++k4) {
            float4 hv = hp[k4];
            unsigned long long h0 = pk2(hv.x, hv.y), h1 = pk2(hv.z, hv.w);
            float4 wa = wr[k4];
            FMA2(rA, pk2(wa.x, wa.y), h0);
            FMA2(rB, pk2(wa.z, wa.w), h1);
            float4 wb = wz[k4];
            FMA2(zA, pk2(wb.x, wb.y), h0);
            FMA2(zB, pk2(wb.z, wb.w), h1);
            float4 wc = wn[k4];
            FMA2(nA, pk2(wc.x, wc.y), h0);
            FMA2(nB, pk2(wc.z, wc.w), h1);
        }
        part[cb][kh][0][lane] = upsum(rA, rB);
        part[cb][kh][1][lane] = upsum(zA, zB);
        part[cb][kh][2][lane] = upsum(nA, nB);
        __syncthreads();

        if (tid < 64) {
            int cc = tid >> 5, b = tid & 31, col = c0 + cc;
            float hr  = part[cc][0][0][b] + part[cc][1][0][b] + bsh[cc * 3 + 0];
            float hz  = part[cc][0][1][b] + part[cc][1][1][b] + bsh[cc * 3 + 1];
            float hn  = part[cc][0][2][b] + part[cc][1][2][b] + bsh[cc * 3 + 2];
            float rg = 1.f / (1.f + expf(-(gis[cc * 3 + 0][b] + hr)));
            float zg = 1.f / (1.f + expf(-(gis[cc * 3 + 1][b] + hz)));
            float ng = tanhf(gis[cc * 3 + 2][b] + rg * hn);
            float hold = ((const float*)hs4)[b * 260 + col];
            float hnew = (1.f - zg) * ng + zg * hold;
            hbuf[(pp ^ 1) * (BB * HHH) + b * HHH + col] = hnew;
            cout[((size_t)t * HHH + col) * BB + b] = hnew;   // [t][k][b] coalesced
            if (t == S - 1) finalh[b * HHH + col] = hnew;
        }
        __syncthreads();
        // release: per-block flag store (parallel across blocks, no atomics)
        if (tid == 0) { __threadfence(); ((volatile int*)flags)[j] = t + 1; }
        pp ^= 1;
    }
}

// ---------------- transpose src[R][K] -> dst[K][R] ---------------------------
__global__ void transpose_kernel(const float* __restrict__ src, float* __restrict__ dst,
                                 int R, int K)
{
    __shared__ float tile[32][33];
    int k0 = blockIdx.x * 32, r0 = blockIdx.y * 32;
    int lx = threadIdx.x, ly = threadIdx.y;   // 32 x 8
    for (int i = ly; i < 32; i += 8) {
        int r = r0 + i, k = k0 + lx;
        tile[i][lx] = (r < R && k < K) ? src[(size_t)r * K + k] : 0.f;
    }
    __syncthreads();
    for (int i = ly; i < 32; i += 8) {
        int k = k0 + i, r = r0 + lx;
        if (k < K && r < R) dst[(size_t)k * R + r] = tile[lx][i];
    }
}

// ---------------- transpose att_w1 -> w1t[f][a] padded to 128 ----------------
__global__ void w1t_kernel(const float* __restrict__ w1, float* __restrict__ w1t)
{
    int idx = blockIdx.x * 256 + threadIdx.x;
    if (idx >= FEAT * 128) return;
    int f = idx >> 7, a = idx & 127;
    w1t[idx] = (a < AAA) ? w1[a * FEAT + f] : 0.f;
}

// ---------------- gather c_sel (from [t][k][b]) + cw = c_sel @ att_weight ----
__global__ void __launch_bounds__(256) cwgather_kernel(
    const float* __restrict__ cout, const int* __restrict__ cindex,
    const float* __restrict__ attw, float* __restrict__ csel, float* __restrict__ cw)
{
    const int r0 = blockIdx.x * 16;
    const int b  = r0 >> 7;
    const int tid = threadIdx.x;
    __shared__ float cs[16][HHH];
    __shared__ int ti[16];
    if (tid < 16) ti[tid] = cindex[b * NNN + ((r0 + tid) & 127)];
    __syncthreads();
    for (int idx = tid; idx < 16 * HHH; idx += 256) {
        int r = idx >> 8, k = idx & 255;
        float v = cout[((size_t)ti[r] * HHH + k) * BB + b];
        cs[r][k] = v;
        csel[(size_t)(r0 + r) * HHH + k] = v;
    }
    __syncthreads();
    float acc[16];
    #pragma unroll
    for (int r = 0; r < 16; ++r) acc[r] = 0.f;
    const int jcol = tid;
    for (int k = 0; k < HHH; ++k) {
        float wk = __ldg(attw + k * HHH + jcol);
        #pragma unroll
        for (int r = 0; r < 16; ++r) acc[r] += cs[r][k] * wk;
    }
    #pragma unroll
    for (int r = 0; r < 16; ++r) cw[(size_t)(r0 + r) * HHH + jcol] = acc[r];
}

// ---------------- per-row dot with per-b vector ------------------------------
__global__ void dot_kernel(const float* __restrict__ mat, const float* __restrict__ vec,
                           float* __restrict__ out)
{
    const int row = blockIdx.x;
    const int b = row >> 7;
    const int tid = threadIdx.x;   // 64
    const float4* mr = (const float4*)(mat + (size_t)row * HHH);
    const float4* vr = (const float4*)(vec + b * HHH);
    float4 a = mr[tid], v = vr[tid];
    float s = a.x * v.x + a.y * v.y + a.z * v.z + a.w * v.w;
    for (int o = 16; o; o >>= 1) s += __shfl_xor_sync(0xffffffffu, s, o);
    __shared__ float sm[2];
    if ((tid & 31) == 0) sm[tid >> 5] = s;
    __syncthreads();
    if (tid == 0) out[row] = sm[0] + sm[1];
}

// ---------------- bterm[b][a] = (b1?) + v[b] . w1t_cols(off..off+256) --------
__global__ void bterm_kernel(const float* __restrict__ v, const float* __restrict__ w1t,
                             const float* __restrict__ b1, int off, float* __restrict__ out)
{
    const int b = blockIdx.x, a = threadIdx.x;   // 128 threads
    __shared__ float vs[HHH];
    for (int i = a; i < HHH; i += 128) vs[i] = v[b * HHH + i];
    __syncthreads();
    float a0 = 0, a1 = 0, a2 = 0, a3 = 0;
    for (int k = 0; k < HHH; k += 4) {
        a0 += vs[k]     * w1t[(off + k) * 128 + a];
        a1 += vs[k + 1] * w1t[(off + k + 1) * 128 + a];
        a2 += vs[k + 2] * w1t[(off + k + 2) * 128 + a];
        a3 += vs[k + 3] * w1t[(off + k + 3) * 128 + a];
    }
    if (a < AAA) out[b * AAA + a] = (b1 ? __ldg(b1 + a) : 0.f) + (a0 + a1) + (a2 + a3);
}

// ---------------- attention projection (T0 precompute or hop+score) ----------
template <bool USEC, bool SCORE>
__global__ void __launch_bounds__(128) attproj_kernel(
    const float* __restrict__ csel, const float* __restrict__ vvec,
    const float* __restrict__ base, const float* __restrict__ dotv,
    const float* __restrict__ w1t, const float* __restrict__ bterm,
    int o2, int o3, int dotcol,
    const float* __restrict__ w2, const float* __restrict__ b2,
    float* __restrict__ outT0, float* __restrict__ outScores)
{
    const int r0 = blockIdx.x * 16;
    const int b  = r0 >> 7;
    const int tid = threadIdx.x;
    __shared__ float cs[16][HHH];
    __shared__ float vs[HHH];
    __shared__ float tvs[16][128];
    for (int idx = tid; idx < 16 * HHH; idx += 128)
        cs[idx >> 8][idx & 255] = csel[(size_t)(r0 + (idx >> 8)) * HHH + (idx & 255)];
    for (int idx = tid; idx < HHH; idx += 128) vs[idx] = vvec[b * HHH + idx];
    __syncthreads();

    const int a = tid;
    const bool va = a < AAA;
    float bt = va ? bterm[b * AAA + a] : 0.f;
    float wd = w1t[dotcol * 128 + a];
    float acc[16];
    #pragma unroll
    for (int r = 0; r < 16; ++r) {
        float v0 = bt + dotv[r0 + r] * wd;
        if (SCORE && va) v0 += base[(size_t)(r0 + r) * AAA + a];
        acc[r] = v0;
    }
    for (int k = 0; k < HHH; ++k) {
        float f1 = USEC ? w1t[k * 128 + a] : 0.f;
        float f2 = w1t[(o2 + k) * 128 + a];
        float f3 = w1t[(o3 + k) * 128 + a];
        float vk = vs[k];
        #pragma unroll
        for (int r = 0; r < 16; ++r) {
            float c = cs[r][k];
            acc[r] += (c * vk) * f2 + fabsf(c - vk) * f3;
            if (USEC) acc[r] += c * f1;
        }
    }
    if (!SCORE) {
        if (va) {
            #pragma unroll
            for (int r = 0; r < 16; ++r) outT0[(size_t)(r0 + r) * AAA + a] = acc[r];
        }
    } else {
        float w2a = va ? __ldg(w2 + a) : 0.f;
        #pragma unroll
        for (int r = 0; r < 16; ++r) tvs[r][a] = va ? tanhf(acc[r]) * w2a : 0.f;
        __syncthreads();
        int wq = tid >> 5, ln = tid & 31;
        #pragma unroll
        for (int rr = 0; rr < 4; ++rr) {
            int row = wq * 4 + rr;
            float s = tvs[row][ln] + tvs[row][ln + 32] + tvs[row][ln + 64] + tvs[row][ln + 96];
            for (int o = 16; o; o >>= 1) s += __shfl_xor_sync(0xffffffffu, s, o);
            if (ln == 0) outScores[r0 + row] = s + __ldg(b2);
        }
    }
}

// ---------------- masked softmax over N=128 ----------------------------------
__global__ void softmaxN_kernel(const float* __restrict__ scores, const int* __restrict__ lenc,
                                float* __restrict__ p, float* __restrict__ attout)
{
    const int b = blockIdx.x, n = threadIdx.x;
    const int lc = lenc[b];
    __shared__ float red[4];
    float s = (n < lc) ? scores[b * NNN + n] : -1e30f;
    float m = s;
    for (int o = 16; o; o >>= 1) m = fmaxf(m, __shfl_xor_sync(0xffffffffu, m, o));
    if ((n & 31) == 0) red[n >> 5] = m;
    __syncthreads();
    m = fmaxf(fmaxf(red[0], red[1]), fmaxf(red[2], red[3]));
    __syncthreads();
    float ev = (n < lc) ? expf(s - m) : 0.f;
    float sum = ev;
    for (int o = 16; o; o >>= 1) sum += __shfl_xor_sync(0xffffffffu, sum, o);
    if ((n & 31) == 0) red[n >> 5] = sum;
    __syncthreads();
    sum = red[0] + red[1] + red[2] + red[3];
    float pv = ev / sum;
    p[b * NNN + n] = pv;
    attout[b * NNN + n] = pv;
}

// ---------------- e[b][k] = sum_n csel[b][n][k] * p[b][n] --------------------
__global__ void __launch_bounds__(256) e_kernel(const float* __restrict__ csel,
                                                const float* __restrict__ p,
                                                float* __restrict__ e)
{
    const int b = blockIdx.x, k = threadIdx.x;
    __shared__ float ps[NNN];
    if (k < NNN) ps[k] = p[b * NNN + k];
    __syncthreads();
    float a0 = 0, a1 = 0;
    for (int n = 0; n < NNN; n += 2) {
        a0 += csel[(size_t)((b << 7) + n) * HHH + k] * ps[n];
        a1 += csel[(size_t)((b << 7) + n + 1) * HHH + k] * ps[n + 1];
    }
    e[b * HHH + k] = a0 + a1;
}

// ---------------- GRU gates via transposed weights ---------------------------
__global__ void __launch_bounds__(256) gates_kernel(
    const float* __restrict__ x1, int k1, const float* __restrict__ x2, int k2,
    const float* __restrict__ h, const float* __restrict__ wti,
    const float* __restrict__ wth, const float* __restrict__ bih,
    const float* __restrict__ bhh, float* __restrict__ gia, float* __restrict__ gha)
{
    const int b = blockIdx.x, rc = blockIdx.y, tid = threadIdx.x;
    const int r = rc * 256 + tid;
    __shared__ float xs[2304];
    __shared__ float hsm[HHH];
    for (int i = tid; i < k1; i += 256) xs[i] = x1[(size_t)b * k1 + i];
    for (int i = tid; i < k2; i += 256) xs[k1 + i] = x2[(size_t)b * k2 + i];
    hsm[tid] = h[b * HHH + tid];
    __syncthreads();
    const int K = k1 + k2;
    float a0 = 0, a1 = 0, a2 = 0, a3 = 0;
    int k = 0;
    for (; k + 4 <= K; k += 4) {
        a0 += xs[k]     * wti[(size_t)k * G3H + r];
        a1 += xs[k + 1] * wti[(size_t)(k + 1) * G3H + r];
        a2 += xs[k + 2] * wti[(size_t)(k + 2) * G3H + r];
        a3 += xs[k + 3] * wti[(size_t)(k + 3) * G3H + r];
    }
    for (; k < K; ++k) a0 += xs[k] * wti[(size_t)k * G3H + r];
    gia[b * G3H + r] = __ldg(bih + r) + (a0 + a1) + (a2 + a3);
    float c0 = 0, c1 = 0, c2 = 0, c3 = 0;
    for (int kk = 0; kk < HHH; kk += 4) {
        c0 += hsm[kk]     * wth[(size_t)kk * G3H + r];
        c1 += hsm[kk + 1] * wth[(size_t)(kk + 1) * G3H + r];
        c2 += hsm[kk + 2] * wth[(size_t)(kk + 2) * G3H + r];
        c3 += hsm[kk + 3] * wth[(size_t)(kk + 3) * G3H + r];
    }
    gha[b * G3H + r] = __ldg(bhh + r) + (c0 + c1) + (c2 + c3);
}

__global__ void __launch_bounds__(256) combine_kernel(
    const float* __restrict__ gia, const float* __restrict__ gha,
    const float* __restrict__ h, float* __restrict__ hout)
{
    const int b = blockIdx.x, k = threadIdx.x;
    float rg = 1.f / (1.f + expf(-(gia[b * G3H + k] + gha[b * G3H + k])));
    float zg = 1.f / (1.f + expf(-(gia[b * G3H + HHH + k] + gha[b * G3H + HHH + k])));
    float ng = tanhf(gia[b * G3H + 2 * HHH + k] + rg * gha[b * G3H + 2 * HHH + k]);
    hout[b * HHH + k] = (1.f - zg) * ng + zg * h[b * HHH + k];
}

// ---------------- logits via transposed out_w --------------------------------
__global__ void __launch_bounds__(256) logits_kernel(
    const float* __restrict__ hv, const float* __restrict__ owt,
    const float* __restrict__ ob, float* __restrict__ y)
{
    const int b = blockIdx.x, tid = threadIdx.x;
    const int o = blockIdx.y * 256 + tid;
    __shared__ float ms[HHH];
    ms[tid] = hv[b * HHH + tid];
    __syncthreads();
    if (o >= OOO) return;
    float a0 = 0, a1 = 0, a2 = 0, a3 = 0;
    for (int k = 0; k < HHH; k += 4) {
        a0 += ms[k]     * owt[(size_t)k * OOO + o];
        a1 += ms[k + 1] * owt[(size_t)(k + 1) * OOO + o];
        a2 += ms[k + 2] * owt[(size_t)(k + 2) * OOO + o];
        a3 += ms[k + 3] * owt[(size_t)(k + 3) * OOO + o];
    }
    y[(size_t)b * OOO + o] = __ldg(ob + o) + (a0 + a1) + (a2 + a3);
}

// ---------------- softmax over O=2000 ----------------------------------------
__global__ void __launch_bounds__(256) softmaxO_kernel(const float* __restrict__ yin,
                                                       float* __restrict__ yout)
{
    const int b = blockIdx.x, tid = threadIdx.x;
    __shared__ float red[8];
    float m = -1e30f;
    for (int o = tid; o < OOO; o += 256) m = fmaxf(m, yin[(size_t)b * OOO + o]);
    for (int o = 16; o; o >>= 1) m = fmaxf(m, __shfl_xor_sync(0xffffffffu, m, o));
    if ((tid & 31) == 0) red[tid >> 5] = m;
    __syncthreads();
    m = red[0];
    #pragma unroll
    for (int i = 1; i < 8; ++i) m = fmaxf(m, red[i]);
    __syncthreads();
    float sum = 0.f;
    for (int o = tid; o < OOO; o += 256) sum += expf(yin[(size_t)b * OOO + o] - m);
    for (int o = 16; o; o >>= 1) sum += __shfl_xor_sync(0xffffffffu, sum, o);
    if ((tid & 31) == 0) red[tid >> 5] = sum;
    __syncthreads();
    sum = 0.f;
    #pragma unroll
    for (int i = 0; i < 8; ++i) sum += red[i];
    float inv = 1.f / sum;
    for (int o = tid; o < OOO; o += 256)
        yout[(size_t)b * OOO + o] = expf(yin[(size_t)b * OOO + o] - m) * inv;
}

__global__ void copy_kernel(const float* __restrict__ s, float* __restrict__ d, int n)
{
    int i = blockIdx.x * 256 + threadIdx.x;
    if (i < n) d[i] = s[i];
}

// ------------------------------- launch --------------------------------------
extern "C" void kernel_launch(void* const* d_in, const int* in_sizes, int n_in,
                              void* d_out, int out_size)
{
    const float* c        = (const float*)d_in[0];
    const float* q        = (const float*)d_in[1];
    const float* i_state  = (const float*)d_in[2];
    const float* q_state  = (const float*)d_in[3];
    const float* in_w_ih  = (const float*)d_in[4];
    const float* in_w_hh  = (const float*)d_in[5];
    const float* in_b_ih  = (const float*)d_in[6];
    const float* in_b_hh  = (const float*)d_in[7];
    const float* qe_w_ih  = (const float*)d_in[8];
    const float* qe_w_hh  = (const float*)d_in[9];
    const float* qe_b_ih  = (const float*)d_in[10];
    const float* qe_b_hh  = (const float*)d_in[11];
    const float* att_weight = (const float*)d_in[12];
    const float* att_w1   = (const float*)d_in[13];
    const float* att_b1   = (const float*)d_in[14];
    const float* att_w2   = (const float*)d_in[15];
    const float* att_b2   = (const float*)d_in[16];
    const float* mem_w_ih = (const float*)d_in[17];
    const float* mem_w_hh = (const float*)d_in[18];
    const float* mem_b_ih = (const float*)d_in[19];
    const float* mem_b_hh = (const float*)d_in[20];
    const float* out_w    = (const float*)d_in[21];
    const float* out_b    = (const float*)d_in[22];
    const float* ans_w_ih = (const float*)d_in[23];
    const float* ans_w_hh = (const float*)d_in[24];
    const float* ans_b_ih = (const float*)d_in[25];
    const float* ans_b_hh = (const float*)d_in[26];
    const int*   c_index  = (const int*)d_in[27];
    const int*   len_c    = (const int*)d_in[28];
    float* out = (float*)d_out;

    float* gb = nullptr;
    cudaGetSymbolAddress((void**)&gb, g_buf);
    int* flags = nullptr;
    cudaGetSymbolAddress((void**)&flags, g_flag);
    int* gen = nullptr;
    cudaGetSymbolAddress((void**)&gen, g_gen);

    float* GI   = gb + OFF_GI;
    float* GIQ  = gb + OFF_GIQ;
    float* HB   = gb + OFF_H;
    float* COUT = gb + OFF_COUT;
    float* QOUT = gb + OFF_QOUT;
    float* QH   = gb + OFF_QH;
    float* HTC  = gb + OFF_HTC;
    float* CSEL = gb + OFF_CSEL;
    float* CW   = gb + OFF_CW;
    float* DOTQ = gb + OFF_DOTQ;
    float* DOTM = gb + OFF_DOTM;
    float* T0   = gb + OFF_T0;
    float* M    = gb + OFF_M;
    float* SC   = gb + OFF_SC;
    float* P    = gb + OFF_P;
    float* E    = gb + OFF_E;
    float* MSQ  = gb + OFF_MSQ;
    float* Y    = gb + OFF_Y;
    float* W1T  = gb + OFF_W1T;
    float* BT   = gb + OFF_BT;
    float* WTAI = gb + OFF_WTAI;
    float* WTAH = gb + OFF_WTAH;
    float* WTMI = gb + OFF_WTMI;
    float* WTMH = gb + OFF_WTMH;
    float* OWT  = gb + OFF_OWT;
    float* GIA  = gb + OFF_GIA;
    float* GHA  = gb + OFF_GHA;

    // ---- weight transposes + w1t (independent prep) ----
    w1t_kernel<<<(FEAT * 128 + 255) / 256, 256>>>(att_w1, W1T);
    {
        dim3 blk(32, 8);
        transpose_kernel<<<dim3((2256 + 31) / 32, 24), blk>>>(ans_w_ih, WTAI, 768, 2256);
        transpose_kernel<<<dim3(8, 24), blk>>>(ans_w_hh, WTAH, 768, 256);
        transpose_kernel<<<dim3(8, 24), blk>>>(mem_w_ih, WTMI, 768, 256);
        transpose_kernel<<<dim3(8, 24), blk>>>(mem_w_hh, WTMH, 768, 256);
        transpose_kernel<<<dim3(8, (2000 + 31) / 32), blk>>>(out_w, OWT, 2000, 256);
    }

    // ---- context GRU ----
    gi_kernel<<<dim3(SSL, 4), 256>>>(c, in_w_ih, in_b_ih, GI, SSL);
    copy_kernel<<<(BB * HHH + 255) / 256, 256>>>(i_state, HB, BB * HHH);
    zeroflags_kernel<<<1, 160>>>(flags, gen);
    rec_kernel<<<129, 128>>>(GI, in_w_hh, in_b_hh, SSL, HB, COUT, HTC, flags, gen);

    // ---- query GRU ----
    gi_kernel<<<dim3(SQQ, 4), 256>>>(q, qe_w_ih, qe_b_ih, GIQ, SQQ);
    copy_kernel<<<(BB * HHH + 255) / 256, 256>>>(q_state, HB, BB * HHH);
    zeroflags_kernel<<<1, 160>>>(flags, gen);
    rec_kernel<<<129, 128>>>(GIQ, qe_w_hh, qe_b_hh, SQQ, HB, QOUT, QH, flags, gen);

    // ---- attention prep ----
    cwgather_kernel<<<BB * NNN / 16, 256>>>(COUT, c_index, att_weight, CSEL, CW);
    dot_kernel<<<BB * NNN, 64>>>(CW, QH, DOTQ);
    bterm_kernel<<<BB, 128>>>(QH, W1T, att_b1, 512, BT);
    attproj_kernel<true, false><<<BB * NNN / 16, 128>>>(
        CSEL, QH, nullptr, DOTQ, W1T, BT, 768, 1280, 1792, nullptr, nullptr, T0, nullptr);
    copy_kernel<<<(BB * HHH + 255) / 256, 256>>>(QH, M, BB * HHH);

    // ---- 3 memory hops ----
    for (int hop = 0; hop < 3; ++hop) {
        dot_kernel<<<BB * NNN, 64>>>(CW, M, DOTM);
        bterm_kernel<<<BB, 128>>>(M, W1T, nullptr, 256, BT);
        attproj_kernel<false, true><<<BB * NNN / 16, 128>>>(
            CSEL, M, T0, DOTM, W1T, BT, 1024, 1536, 1793, att_w2, att_b2, nullptr, SC);
        softmaxN_kernel<<<BB, NNN>>>(SC, len_c, P, out + BB * OOO + hop * BB * NNN);
        e_kernel<<<BB, HHH>>>(CSEL, P, E);
        gates_kernel<<<dim3(BB, 3), 256>>>(E, HHH, nullptr, 0, M,
                                           WTMI, WTMH, mem_b_ih, mem_b_hh, GIA, GHA);
        combine_kernel<<<BB, 256>>>(GIA, GHA, M, M);
    }

    // ---- answer loop ----
    copy_kernel<<<(BB * HHH + 255) / 256, 256>>>(M, MSQ, BB * HHH);
    for (int t = 0; t < 2; ++t) {
        logits_kernel<<<dim3(BB, 8), 256>>>(MSQ, OWT, out_b, Y);
        softmaxO_kernel<<<BB, 256>>>(Y, Y);
        gates_kernel<<<dim3(BB, 3), 256>>>(Y, OOO, QH, HHH, MSQ,
                                           WTAI, WTAH, ans_b_ih, ans_b_hh, GIA, GHA);
        combine_kernel<<<BB, 256>>>(GIA, GHA, MSQ, MSQ);
    }
    logits_kernel<<<dim3(BB, 8), 256>>>(MSQ, OWT, out_b, Y);
    softmaxO_kernel<<<BB, 256>>>(Y, out);
}

// round 13
// speedup vs baseline: 1.4554x; 1.2315x over previous
#include <cuda_runtime.h>
#include <math.h>
#include <stdint.h>

// Problem constants
#define BB   32
#define SSL  1024
#define SQQ  32
#define NNN  128
#define DINN 128
#define HHH  256
#define AAA  100
#define OOO  2000
#define G3H  768
#define FEAT 1794   // 7*H + 2
#define CLUSTER 8

// ---------------- scratch offsets (floats) in one big device buffer ----------
#define OFF_GI    0UL          // 1024*32*768  [t][b][row]
#define OFF_GIQ   25165824UL   // 32*32*768
#define OFF_COUT  25968640UL   // 1024*32*256  [t][b][k]
#define OFF_QOUT  34357248UL   // 32*32*256
#define OFF_QH    34619392UL   // 32*256
#define OFF_HTC   34627584UL   // 32*256
#define OFF_CSEL  34635776UL   // 32*128*256
#define OFF_CW    35684352UL   // 32*128*256
#define OFF_DOTQ  36732928UL   // 4096
#define OFF_DOTM  36737024UL   // 4096
#define OFF_T0    36741120UL   // 4096*100
#define OFF_M     37150720UL   // 32*256
#define OFF_SC    37158912UL   // 4096
#define OFF_P     37163008UL   // 4096
#define OFF_E     37167104UL   // 32*256
#define OFF_MSQ   37175296UL   // 32*256
#define OFF_Y     37183488UL   // 32*2000
#define OFF_W1T   37247488UL   // 1794*128
#define OFF_BT    37477120UL   // 32*100
#define OFF_WTAI  37480320UL   // 2256*768
#define OFF_WTAH  39212928UL   // 256*768
#define OFF_WTMI  39409536UL   // 256*768
#define OFF_WTMH  39606144UL   // 256*768
#define OFF_OWT   39802752UL   // 256*2000
#define OFF_GIA   40314752UL   // 32*768
#define OFF_GHA   40339328UL   // 32*768
#define TOTALF    40363904UL

__device__ __align__(16) float g_buf[TOTALF];

// ---------------- packed f32x2 FMA helpers (sm_103a) -------------------------
__device__ __forceinline__ unsigned long long pk2(float x, float y) {
    unsigned long long r;
    asm("mov.b64 %0, {%1, %2};" : "=l"(r) : "f"(x), "f"(y));
    return r;
}
__device__ __forceinline__ float upsum(unsigned long long a, unsigned long long b) {
    float ax, ay, bx, by;
    asm("mov.b64 {%0, %1}, %2;" : "=f"(ax), "=f"(ay) : "l"(a));
    asm("mov.b64 {%0, %1}, %2;" : "=f"(bx), "=f"(by) : "l"(b));
    return (ax + ay) + (bx + by);
}
#define FMA2(acc, a, b) \
    asm("fma.rn.f32x2 %0, %1, %2, %0;" : "+l"(acc) : "l"(a), "l"(b))

// ---------------- cluster helpers ---------------------------------------------
__device__ __forceinline__ uint32_t smem_u32(const void* p) {
    uint32_t a;
    asm("{ .reg .u64 t; cvta.to.shared.u64 t, %1; cvt.u32.u64 %0, t; }"
        : "=r"(a) : "l"(p));
    return a;
}
__device__ __forceinline__ uint32_t cluster_rank() {
    uint32_t r;
    asm("mov.u32 %0, %%cluster_ctarank;" : "=r"(r));
    return r;
}
__device__ __forceinline__ uint32_t mapa_u32(uint32_t addr, uint32_t rank) {
    uint32_t r;
    asm("mapa.shared::cluster.u32 %0, %1, %2;" : "=r"(r) : "r"(addr), "r"(rank));
    return r;
}
__device__ __forceinline__ void st_cluster_f32(uint32_t addr, float v) {
    asm volatile("st.shared::cluster.f32 [%0], %1;" :: "r"(addr), "f"(v) : "memory");
}
__device__ __forceinline__ void cluster_sync() {
    asm volatile("barrier.cluster.arrive.aligned;" ::: "memory");
    asm volatile("barrier.cluster.wait.aligned;" ::: "memory");
}

// ---------------- gi = x @ w_ih^T + b_ih  ->  out[t][b][row] ------------------
// grid (S, 4): blockIdx.y selects a 192-row chunk. Compute with 4-row register
// blocking, then smem-transpose so global writes are coalesced over rows.
__global__ void __launch_bounds__(256) gi_kernel(
    const float* __restrict__ x, const float* __restrict__ w,
    const float* __restrict__ bias, float* __restrict__ out, int S)
{
    const int t = blockIdx.x;
    const int rbase = blockIdx.y * 192;
    __shared__ float4 xs4[32][33];    // [b][k4]
    __shared__ float  tile[192][33];  // [rr][b]
    for (int idx = threadIdx.x; idx < 1024; idx += 256) {
        int b = idx >> 5, k4 = idx & 31;
        xs4[b][k4] = __ldg(((const float4*)x) + ((size_t)b * S + t) * 32 + k4);
    }
    __syncthreads();
    const int b = threadIdx.x & 31, w0 = threadIdx.x >> 5;
    for (int r = rbase + w0 * 4; r < rbase + 192; r += 32) {
        const float4* wr0 = (const float4*)(w + (size_t)r * DINN);
        const float4* wr1 = wr0 + 32;
        const float4* wr2 = wr0 + 64;
        const float4* wr3 = wr0 + 96;
        float s[4][4];
        #pragma unroll
        for (int i = 0; i < 4; ++i)
            #pragma unroll
            for (int jj = 0; jj < 4; ++jj) s[i][jj] = 0.f;
        #pragma unroll
        for (int k4 = 0; k4 < 32; ++k4) {
            float4 xv = xs4[b][k4];
            float4 w0v = __ldg(wr0 + k4), w1v = __ldg(wr1 + k4);
            float4 w2v = __ldg(wr2 + k4), w3v = __ldg(wr3 + k4);
            s[0][0] += w0v.x * xv.x; s[0][1] += w0v.y * xv.y; s[0][2] += w0v.z * xv.z; s[0][3] += w0v.w * xv.w;
            s[1][0] += w1v.x * xv.x; s[1][1] += w1v.y * xv.y; s[1][2] += w1v.z * xv.z; s[1][3] += w1v.w * xv.w;
            s[2][0] += w2v.x * xv.x; s[2][1] += w2v.y * xv.y; s[2][2] += w2v.z * xv.z; s[2][3] += w2v.w * xv.w;
            s[3][0] += w3v.x * xv.x; s[3][1] += w3v.y * xv.y; s[3][2] += w3v.z * xv.z; s[3][3] += w3v.w * xv.w;
        }
        #pragma unroll
        for (int i = 0; i < 4; ++i)
            tile[r - rbase + i][b] =
                __ldg(bias + r + i) + (s[i][0] + s[i][1]) + (s[i][2] + s[i][3]);
    }
    __syncthreads();
    for (int idx = threadIdx.x; idx < 192 * 32; idx += 256) {
        int bb = idx / 192, rr = idx % 192;
        out[((size_t)t * BB + bb) * G3H + rbase + rr] = tile[rr][bb];
    }
}

// ---------------- cluster GRU recurrence ---------------------------------------
// 16 clusters x 8 CTAs x 192 threads. Cluster c owns batches {2c, 2c+1};
// rank r owns h columns [32r, 32r+32). Weights live in REGISTERS (32 float4
// per thread). h ping-pongs in smem; each step's 64 new h values are DSMEM-
// broadcast to all 8 CTAs, ordered by one barrier.cluster (release/acquire).
__global__ void __launch_bounds__(192, 1) __cluster_dims__(CLUSTER, 1, 1)
rec_kernel(const float* __restrict__ gi, const float* __restrict__ whh,
           const float* __restrict__ bhh, int S,
           const float* __restrict__ h0,
           float* __restrict__ cout, float* __restrict__ finalh)
{
    __shared__ __align__(16) float hbuf[2][2][HHH];   // [pp][b][k]
    __shared__ float part[3][2][2][32];               // [g][kh][b][col]

    const int tid = threadIdx.x;
    const int w = tid >> 5, lane = tid & 31;
    const int g = w >> 1, kh = w & 1;                 // gate, k-half
    const uint32_t rank = cluster_rank();
    const int cid = blockIdx.x / CLUSTER;
    const int bg0 = cid * 2;
    const int colg = (int)rank * 32 + lane;

    // weights -> registers: row (g*256 + colg), half kh
    float4 wreg[32];
    {
        const float4* src = (const float4*)(whh + ((size_t)g * HHH + colg) * HHH + kh * 128);
        #pragma unroll
        for (int i = 0; i < 32; ++i) wreg[i] = __ldg(src + i);
    }

    // combine-thread constants (threads 0..63: warp0 -> b=0, warp1 -> b=1)
    int cb = 0, ccolg = 0;
    float bh0 = 0.f, bh1 = 0.f, bh2 = 0.f;
    if (tid < 64) {
        cb = tid >> 5;
        ccolg = (int)rank * 32 + (tid & 31);
        bh0 = __ldg(bhh + 0 * HHH + ccolg);
        bh1 = __ldg(bhh + 1 * HHH + ccolg);
        bh2 = __ldg(bhh + 2 * HHH + ccolg);
    }

    // init h (each CTA keeps a full local copy of h for its 2 batches)
    for (int i = tid; i < 2 * HHH; i += 192) {
        int b = i >> 8, k = i & 255;
        hbuf[0][b][k] = h0[(bg0 + b) * HHH + k];
    }

    // prefetch gi[0]
    float gr = 0.f, gz = 0.f, gn = 0.f;
    if (tid < 64) {
        const float* gp = gi + ((size_t)0 * BB + bg0 + cb) * G3H;
        gr = __ldcg(gp + 0 * HHH + ccolg);
        gz = __ldcg(gp + 1 * HHH + ccolg);
        gn = __ldcg(gp + 2 * HHH + ccolg);
    }
    __syncthreads();
    cluster_sync();

    int pp = 0;
    for (int t = 0; t < S; ++t) {
        // 3-gate dot, weights in regs, h reads are warp-broadcast LDS
        unsigned long long a0x = 0, a0y = 0, a1x = 0, a1y = 0;
        const float4* hb0 = (const float4*)(hbuf[pp][0] + kh * 128);
        const float4* hb1 = (const float4*)(hbuf[pp][1] + kh * 128);
        #pragma unroll
        for (int k4 = 0; k4 < 32; ++k4) {
            float4 wv = wreg[k4];
            unsigned long long wxy = pk2(wv.x, wv.y), wzw = pk2(wv.z, wv.w);
            float4 h0v = hb0[k4];
            FMA2(a0x, wxy, pk2(h0v.x, h0v.y));
            FMA2(a0y, wzw, pk2(h0v.z, h0v.w));
            float4 h1v = hb1[k4];
            FMA2(a1x, wxy, pk2(h1v.x, h1v.y));
            FMA2(a1y, wzw, pk2(h1v.z, h1v.w));
        }
        part[g][kh][0][lane] = upsum(a0x, a0y);
        part[g][kh][1][lane] = upsum(a1x, a1y);
        __syncthreads();

        if (tid < 64) {
            int ccol = tid & 31;
            float hr = part[0][0][cb][ccol] + part[0][1][cb][ccol] + bh0;
            float hz = part[1][0][cb][ccol] + part[1][1][cb][ccol] + bh1;
            float hn = part[2][0][cb][ccol] + part[2][1][cb][ccol] + bh2;
            float rg = 1.f / (1.f + expf(-(gr + hr)));
            float zg = 1.f / (1.f + expf(-(gz + hz)));
            float ng = tanhf(gn + rg * hn);
            float hold = hbuf[pp][cb][ccolg];
            float hnew = (1.f - zg) * ng + zg * hold;
            cout[((size_t)t * BB + bg0 + cb) * HHH + ccolg] = hnew;
            if (t == S - 1) finalh[(bg0 + cb) * HHH + ccolg] = hnew;
            // prefetch next gi (overlaps with DSMEM + cluster barrier)
            if (t + 1 < S) {
                const float* gp = gi + ((size_t)(t + 1) * BB + bg0 + cb) * G3H;
                gr = __ldcg(gp + 0 * HHH + ccolg);
                gz = __ldcg(gp + 1 * HHH + ccolg);
                gn = __ldcg(gp + 2 * HHH + ccolg);
            }
            // DSMEM broadcast of hnew to all 8 CTAs (incl. self)
            uint32_t laddr = smem_u32(&hbuf[pp ^ 1][cb][ccolg]);
            #pragma unroll
            for (uint32_t p = 0; p < CLUSTER; ++p)
                st_cluster_f32(mapa_u32(laddr, p), hnew);
        }
        // barrier.cluster: arrive releases the DSMEM stores, wait acquires them
        cluster_sync();
        pp ^= 1;
    }
}

// ---------------- transpose src[R][K] -> dst[K][R] ---------------------------
__global__ void transpose_kernel(const float* __restrict__ src, float* __restrict__ dst,
                                 int R, int K)
{
    __shared__ float tile[32][33];
    int k0 = blockIdx.x * 32, r0 = blockIdx.y * 32;
    int lx = threadIdx.x, ly = threadIdx.y;   // 32 x 8
    for (int i = ly; i < 32; i += 8) {
        int r = r0 + i, k = k0 + lx;
        tile[i][lx] = (r < R && k < K) ? src[(size_t)r * K + k] : 0.f;
    }
    __syncthreads();
    for (int i = ly; i < 32; i += 8) {
        int k = k0 + i, r = r0 + lx;
        if (k < K && r < R) dst[(size_t)k * R + r] = tile[lx][i];
    }
}

// ---------------- transpose att_w1 -> w1t[f][a] padded to 128 ----------------
__global__ void w1t_kernel(const float* __restrict__ w1, float* __restrict__ w1t)
{
    int idx = blockIdx.x * 256 + threadIdx.x;
    if (idx >= FEAT * 128) return;
    int f = idx >> 7, a = idx & 127;
    w1t[idx] = (a < AAA) ? w1[a * FEAT + f] : 0.f;
}

// ---------------- gather c_sel (from [t][b][k]) + cw = c_sel @ att_weight ----
__global__ void __launch_bounds__(256) cwgather_kernel(
    const float* __restrict__ cout, const int* __restrict__ cindex,
    const float* __restrict__ attw, float* __restrict__ csel, float* __restrict__ cw)
{
    const int r0 = blockIdx.x * 16;
    const int b  = r0 >> 7;
    const int tid = threadIdx.x;
    __shared__ float cs[16][HHH];
    __shared__ int ti[16];
    if (tid < 16) ti[tid] = cindex[b * NNN + ((r0 + tid) & 127)];
    __syncthreads();
    for (int idx = tid; idx < 16 * HHH; idx += 256) {
        int r = idx >> 8, k = idx & 255;
        float v = cout[((size_t)ti[r] * BB + b) * HHH + k];
        cs[r][k] = v;
        csel[(size_t)(r0 + r) * HHH + k] = v;
    }
    __syncthreads();
    float acc[16];
    #pragma unroll
    for (int r = 0; r < 16; ++r) acc[r] = 0.f;
    const int jcol = tid;
    for (int k = 0; k < HHH; ++k) {
        float wk = __ldg(attw + k * HHH + jcol);
        #pragma unroll
        for (int r = 0; r < 16; ++r) acc[r] += cs[r][k] * wk;
    }
    #pragma unroll
    for (int r = 0; r < 16; ++r) cw[(size_t)(r0 + r) * HHH + jcol] = acc[r];
}

// ---------------- per-row dot with per-b vector ------------------------------
__global__ void dot_kernel(const float* __restrict__ mat, const float* __restrict__ vec,
                           float* __restrict__ out)
{
    const int row = blockIdx.x;
    const int b = row >> 7;
    const int tid = threadIdx.x;   // 64
    const float4* mr = (const float4*)(mat + (size_t)row * HHH);
    const float4* vr = (const float4*)(vec + b * HHH);
    float4 a = mr[tid], v = vr[tid];
    float s = a.x * v.x + a.y * v.y + a.z * v.z + a.w * v.w;
    for (int o = 16; o; o >>= 1) s += __shfl_xor_sync(0xffffffffu, s, o);
    __shared__ float sm[2];
    if ((tid & 31) == 0) sm[tid >> 5] = s;
    __syncthreads();
    if (tid == 0) out[row] = sm[0] + sm[1];
}

// ---------------- bterm[b][a] = (b1?) + v[b] . w1t_cols(off..off+256) --------
__global__ void bterm_kernel(const float* __restrict__ v, const float* __restrict__ w1t,
                             const float* __restrict__ b1, int off, float* __restrict__ out)
{
    const int b = blockIdx.x, a = threadIdx.x;   // 128 threads
    __shared__ float vs[HHH];
    for (int i = a; i < HHH; i += 128) vs[i] = v[b * HHH + i];
    __syncthreads();
    float a0 = 0, a1 = 0, a2 = 0, a3 = 0;
    for (int k = 0; k < HHH; k += 4) {
        a0 += vs[k]     * w1t[(off + k) * 128 + a];
        a1 += vs[k + 1] * w1t[(off + k + 1) * 128 + a];
        a2 += vs[k + 2] * w1t[(off + k + 2) * 128 + a];
        a3 += vs[k + 3] * w1t[(off + k + 3) * 128 + a];
    }
    if (a < AAA) out[b * AAA + a] = (b1 ? __ldg(b1 + a) : 0.f) + (a0 + a1) + (a2 + a3);
}

// ---------------- attention projection (T0 precompute or hop+score) ----------
template <bool USEC, bool SCORE>
__global__ void __launch_bounds__(128) attproj_kernel(
    const float* __restrict__ csel, const float* __restrict__ vvec,
    const float* __restrict__ base, const float* __restrict__ dotv,
    const float* __restrict__ w1t, const float* __restrict__ bterm,
    int o2, int o3, int dotcol,
    const float* __restrict__ w2, const float* __restrict__ b2,
    float* __restrict__ outT0, float* __restrict__ outScores)
{
    const int r0 = blockIdx.x * 16;
    const int b  = r0 >> 7;
    const int tid = threadIdx.x;
    __shared__ float cs[16][HHH];
    __shared__ float vs[HHH];
    __shared__ float tvs[16][128];
    for (int idx = tid; idx < 16 * HHH; idx += 128)
        cs[idx >> 8][idx & 255] = csel[(size_t)(r0 + (idx >> 8)) * HHH + (idx & 255)];
    for (int idx = tid; idx < HHH; idx += 128) vs[idx] = vvec[b * HHH + idx];
    __syncthreads();

    const int a = tid;
    const bool va = a < AAA;
    float bt = va ? bterm[b * AAA + a] : 0.f;
    float wd = w1t[dotcol * 128 + a];
    float acc[16];
    #pragma unroll
    for (int r = 0; r < 16; ++r) {
        float v0 = bt + dotv[r0 + r] * wd;
        if (SCORE && va) v0 += base[(size_t)(r0 + r) * AAA + a];
        acc[r] = v0;
    }
    for (int k = 0; k < HHH; ++k) {
        float f1 = USEC ? w1t[k * 128 + a] : 0.f;
        float f2 = w1t[(o2 + k) * 128 + a];
        float f3 = w1t[(o3 + k) * 128 + a];
        float vk = vs[k];
        #pragma unroll
        for (int r = 0; r < 16; ++r) {
            float c = cs[r][k];
            acc[r] += (c * vk) * f2 + fabsf(c - vk) * f3;
            if (USEC) acc[r] += c * f1;
        }
    }
    if (!SCORE) {
        if (va) {
            #pragma unroll
            for (int r = 0; r < 16; ++r) outT0[(size_t)(r0 + r) * AAA + a] = acc[r];
        }
    } else {
        float w2a = va ? __ldg(w2 + a) : 0.f;
        #pragma unroll
        for (int r = 0; r < 16; ++r) tvs[r][a] = va ? tanhf(acc[r]) * w2a : 0.f;
        __syncthreads();
        int wq = tid >> 5, ln = tid & 31;
        #pragma unroll
        for (int rr = 0; rr < 4; ++rr) {
            int row = wq * 4 + rr;
            float s = tvs[row][ln] + tvs[row][ln + 32] + tvs[row][ln + 64] + tvs[row][ln + 96];
            for (int o = 16; o; o >>= 1) s += __shfl_xor_sync(0xffffffffu, s, o);
            if (ln == 0) outScores[r0 + row] = s + __ldg(b2);
        }
    }
}

// ---------------- masked softmax over N=128 ----------------------------------
__global__ void softmaxN_kernel(const float* __restrict__ scores, const int* __restrict__ lenc,
                                float* __restrict__ p, float* __restrict__ attout)
{
    const int b = blockIdx.x, n = threadIdx.x;
    const int lc = lenc[b];
    __shared__ float red[4];
    float s = (n < lc) ? scores[b * NNN + n] : -1e30f;
    float m = s;
    for (int o = 16; o; o >>= 1) m = fmaxf(m, __shfl_xor_sync(0xffffffffu, m, o));
    if ((n & 31) == 0) red[n >> 5] = m;
    __syncthreads();
    m = fmaxf(fmaxf(red[0], red[1]), fmaxf(red[2], red[3]));
    __syncthreads();
    float ev = (n < lc) ? expf(s - m) : 0.f;
    float sum = ev;
    for (int o = 16; o; o >>= 1) sum += __shfl_xor_sync(0xffffffffu, sum, o);
    if ((n & 31) == 0) red[n >> 5] = sum;
    __syncthreads();
    sum = red[0] + red[1] + red[2] + red[3];
    float pv = ev / sum;
    p[b * NNN + n] = pv;
    attout[b * NNN + n] = pv;
}

// ---------------- e[b][k] = sum_n csel[b][n][k] * p[b][n] --------------------
__global__ void __launch_bounds__(256) e_kernel(const float* __restrict__ csel,
                                                const float* __restrict__ p,
                                                float* __restrict__ e)
{
    const int b = blockIdx.x, k = threadIdx.x;
    __shared__ float ps[NNN];
    if (k < NNN) ps[k] = p[b * NNN + k];
    __syncthreads();
    float a0 = 0, a1 = 0;
    for (int n = 0; n < NNN; n += 2) {
        a0 += csel[(size_t)((b << 7) + n) * HHH + k] * ps[n];
        a1 += csel[(size_t)((b << 7) + n + 1) * HHH + k] * ps[n + 1];
    }
    e[b * HHH + k] = a0 + a1;
}

// ---------------- GRU gates via transposed weights ---------------------------
__global__ void __launch_bounds__(256) gates_kernel(
    const float* __restrict__ x1, int k1, const float* __restrict__ x2, int k2,
    const float* __restrict__ h, const float* __restrict__ wti,
    const float* __restrict__ wth, const float* __restrict__ bih,
    const float* __restrict__ bhh, float* __restrict__ gia, float* __restrict__ gha)
{
    const int b = blockIdx.x, rc = blockIdx.y, tid = threadIdx.x;
    const int r = rc * 256 + tid;
    __shared__ float xs[2304];
    __shared__ float hsm[HHH];
    for (int i = tid; i < k1; i += 256) xs[i] = x1[(size_t)b * k1 + i];
    for (int i = tid; i < k2; i += 256) xs[k1 + i] = x2[(size_t)b * k2 + i];
    hsm[tid] = h[b * HHH + tid];
    __syncthreads();
    const int K = k1 + k2;
    float a0 = 0, a1 = 0, a2 = 0, a3 = 0;
    int k = 0;
    for (; k + 4 <= K; k += 4) {
        a0 += xs[k]     * wti[(size_t)k * G3H + r];
        a1 += xs[k + 1] * wti[(size_t)(k + 1) * G3H + r];
        a2 += xs[k + 2] * wti[(size_t)(k + 2) * G3H + r];
        a3 += xs[k + 3] * wti[(size_t)(k + 3) * G3H + r];
    }
    for (; k < K; ++k) a0 += xs[k] * wti[(size_t)k * G3H + r];
    gia[b * G3H + r] = __ldg(bih + r) + (a0 + a1) + (a2 + a3);
    float c0 = 0, c1 = 0, c2 = 0, c3 = 0;
    for (int kk = 0; kk < HHH; kk += 4) {
        c0 += hsm[kk]     * wth[(size_t)kk * G3H + r];
        c1 += hsm[kk + 1] * wth[(size_t)(kk + 1) * G3H + r];
        c2 += hsm[kk + 2] * wth[(size_t)(kk + 2) * G3H + r];
        c3 += hsm[kk + 3] * wth[(size_t)(kk + 3) * G3H + r];
    }
    gha[b * G3H + r] = __ldg(bhh + r) + (c0 + c1) + (c2 + c3);
}

__global__ void __launch_bounds__(256) combine_kernel(
    const float* __restrict__ gia, const float* __restrict__ gha,
    const float* __restrict__ h, float* __restrict__ hout)
{
    const int b = blockIdx.x, k = threadIdx.x;
    float rg = 1.f / (1.f + expf(-(gia[b * G3H + k] + gha[b * G3H + k])));
    float zg = 1.f / (1.f + expf(-(gia[b * G3H + HHH + k] + gha[b * G3H + HHH + k])));
    float ng = tanhf(gia[b * G3H + 2 * HHH + k] + rg * gha[b * G3H + 2 * HHH + k]);
    hout[b * HHH + k] = (1.f - zg) * ng + zg * h[b * HHH + k];
}

// ---------------- logits via transposed out_w --------------------------------
__global__ void __launch_bounds__(256) logits_kernel(
    const float* __restrict__ hv, const float* __restrict__ owt,
    const float* __restrict__ ob, float* __restrict__ y)
{
    const int b = blockIdx.x, tid = threadIdx.x;
    const int o = blockIdx.y * 256 + tid;
    __shared__ float ms[HHH];
    ms[tid] = hv[b * HHH + tid];
    __syncthreads();
    if (o >= OOO) return;
    float a0 = 0, a1 = 0, a2 = 0, a3 = 0;
    for (int k = 0; k < HHH; k += 4) {
        a0 += ms[k]     * owt[(size_t)k * OOO + o];
        a1 += ms[k + 1] * owt[(size_t)(k + 1) * OOO + o];
        a2 += ms[k + 2] * owt[(size_t)(k + 2) * OOO + o];
        a3 += ms[k + 3] * owt[(size_t)(k + 3) * OOO + o];
    }
    y[(size_t)b * OOO + o] = __ldg(ob + o) + (a0 + a1) + (a2 + a3);
}

// ---------------- softmax over O=2000 ----------------------------------------
__global__ void __launch_bounds__(256) softmaxO_kernel(const float* __restrict__ yin,
                                                       float* __restrict__ yout)
{
    const int b = blockIdx.x, tid = threadIdx.x;
    __shared__ float red[8];
    float m = -1e30f;
    for (int o = tid; o < OOO; o += 256) m = fmaxf(m, yin[(size_t)b * OOO + o]);
    for (int o = 16; o; o >>= 1) m = fmaxf(m, __shfl_xor_sync(0xffffffffu, m, o));
    if ((tid & 31) == 0) red[tid >> 5] = m;
    __syncthreads();
    m = red[0];
    #pragma unroll
    for (int i = 1; i < 8; ++i) m = fmaxf(m, red[i]);
    __syncthreads();
    float sum = 0.f;
    for (int o = tid; o < OOO; o += 256) sum += expf(yin[(size_t)b * OOO + o] - m);
    for (int o = 16; o; o >>= 1) sum += __shfl_xor_sync(0xffffffffu, sum, o);
    if ((tid & 31) == 0) red[tid >> 5] = sum;
    __syncthreads();
    sum = 0.f;
    #pragma unroll
    for (int i = 0; i < 8; ++i) sum += red[i];
    float inv = 1.f / sum;
    for (int o = tid; o < OOO; o += 256)
        yout[(size_t)b * OOO + o] = expf(yin[(size_t)b * OOO + o] - m) * inv;
}

__global__ void copy_kernel(const float* __restrict__ s, float* __restrict__ d, int n)
{
    int i = blockIdx.x * 256 + threadIdx.x;
    if (i < n) d[i] = s[i];
}

// ------------------------------- launch --------------------------------------
extern "C" void kernel_launch(void* const* d_in, const int* in_sizes, int n_in,
                              void* d_out, int out_size)
{
    const float* c        = (const float*)d_in[0];
    const float* q        = (const float*)d_in[1];
    const float* i_state  = (const float*)d_in[2];
    const float* q_state  = (const float*)d_in[3];
    const float* in_w_ih  = (const float*)d_in[4];
    const float* in_w_hh  = (const float*)d_in[5];
    const float* in_b_ih  = (const float*)d_in[6];
    const float* in_b_hh  = (const float*)d_in[7];
    const float* qe_w_ih  = (const float*)d_in[8];
    const float* qe_w_hh  = (const float*)d_in[9];
    const float* qe_b_ih  = (const float*)d_in[10];
    const float* qe_b_hh  = (const float*)d_in[11];
    const float* att_weight = (const float*)d_in[12];
    const float* att_w1   = (const float*)d_in[13];
    const float* att_b1   = (const float*)d_in[14];
    const float* att_w2   = (const float*)d_in[15];
    const float* att_b2   = (const float*)d_in[16];
    const float* mem_w_ih = (const float*)d_in[17];
    const float* mem_w_hh = (const float*)d_in[18];
    const float* mem_b_ih = (const float*)d_in[19];
    const float* mem_b_hh = (const float*)d_in[20];
    const float* out_w    = (const float*)d_in[21];
    const float* out_b    = (const float*)d_in[22];
    const float* ans_w_ih = (const float*)d_in[23];
    const float* ans_w_hh = (const float*)d_in[24];
    const float* ans_b_ih = (const float*)d_in[25];
    const float* ans_b_hh = (const float*)d_in[26];
    const int*   c_index  = (const int*)d_in[27];
    const int*   len_c    = (const int*)d_in[28];
    float* out = (float*)d_out;

    float* gb = nullptr;
    cudaGetSymbolAddress((void**)&gb, g_buf);

    float* GI   = gb + OFF_GI;
    float* GIQ  = gb + OFF_GIQ;
    float* COUT = gb + OFF_COUT;
    float* QOUT = gb + OFF_QOUT;
    float* QH   = gb + OFF_QH;
    float* HTC  = gb + OFF_HTC;
    float* CSEL = gb + OFF_CSEL;
    float* CW   = gb + OFF_CW;
    float* DOTQ = gb + OFF_DOTQ;
    float* DOTM = gb + OFF_DOTM;
    float* T0   = gb + OFF_T0;
    float* M    = gb + OFF_M;
    float* SC   = gb + OFF_SC;
    float* P    = gb + OFF_P;
    float* E    = gb + OFF_E;
    float* MSQ  = gb + OFF_MSQ;
    float* Y    = gb + OFF_Y;
    float* W1T  = gb + OFF_W1T;
    float* BT   = gb + OFF_BT;
    float* WTAI = gb + OFF_WTAI;
    float* WTAH = gb + OFF_WTAH;
    float* WTMI = gb + OFF_WTMI;
    float* WTMH = gb + OFF_WTMH;
    float* OWT  = gb + OFF_OWT;
    float* GIA  = gb + OFF_GIA;
    float* GHA  = gb + OFF_GHA;

    dim3 tblk(32, 8);

    // Launch order places rec_kernel (context) at launch #6 so ncu (-s 5 -c 1)
    // profiles the recurrence instead of a transpose.
    gi_kernel<<<dim3(SSL, 4), 256>>>(c, in_w_ih, in_b_ih, GI, SSL);          // 1
    w1t_kernel<<<(FEAT * 128 + 255) / 256, 256>>>(att_w1, W1T);              // 2
    transpose_kernel<<<dim3((2256 + 31) / 32, 24), tblk>>>(ans_w_ih, WTAI, 768, 2256); // 3
    transpose_kernel<<<dim3(8, 24), tblk>>>(ans_w_hh, WTAH, 768, 256);       // 4
    transpose_kernel<<<dim3(8, 24), tblk>>>(mem_w_ih, WTMI, 768, 256);       // 5
    rec_kernel<<<128, 192>>>(GI, in_w_hh, in_b_hh, SSL, i_state, COUT, HTC); // 6 <- ncu
    transpose_kernel<<<dim3(8, 24), tblk>>>(mem_w_hh, WTMH, 768, 256);       // 7
    transpose_kernel<<<dim3(8, (2000 + 31) / 32), tblk>>>(out_w, OWT, 2000, 256); // 8

    // ---- query GRU ----
    gi_kernel<<<dim3(SQQ, 4), 256>>>(q, qe_w_ih, qe_b_ih, GIQ, SQQ);
    rec_kernel<<<128, 192>>>(GIQ, qe_w_hh, qe_b_hh, SQQ, q_state, QOUT, QH);

    // ---- attention prep ----
    cwgather_kernel<<<BB * NNN / 16, 256>>>(COUT, c_index, att_weight, CSEL, CW);
    dot_kernel<<<BB * NNN, 64>>>(CW, QH, DOTQ);
    bterm_kernel<<<BB, 128>>>(QH, W1T, att_b1, 512, BT);
    attproj_kernel<true, false><<<BB * NNN / 16, 128>>>(
        CSEL, QH, nullptr, DOTQ, W1T, BT, 768, 1280, 1792, nullptr, nullptr, T0, nullptr);
    copy_kernel<<<(BB * HHH + 255) / 256, 256>>>(QH, M, BB * HHH);

    // ---- 3 memory hops ----
    for (int hop = 0; hop < 3; ++hop) {
        dot_kernel<<<BB * NNN, 64>>>(CW, M, DOTM);
        bterm_kernel<<<BB, 128>>>(M, W1T, nullptr, 256, BT);
        attproj_kernel<false, true><<<BB * NNN / 16, 128>>>(
            CSEL, M, T0, DOTM, W1T, BT, 1024, 1536, 1793, att_w2, att_b2, nullptr, SC);
        softmaxN_kernel<<<BB, NNN>>>(SC, len_c, P, out + BB * OOO + hop * BB * NNN);
        e_kernel<<<BB, HHH>>>(CSEL, P, E);
        gates_kernel<<<dim3(BB, 3), 256>>>(E, HHH, nullptr, 0, M,
                                           WTMI, WTMH, mem_b_ih, mem_b_hh, GIA, GHA);
        combine_kernel<<<BB, 256>>>(GIA, GHA, M, M);
    }

    // ---- answer loop ----
    copy_kernel<<<(BB * HHH + 255) / 256, 256>>>(M, MSQ, BB * HHH);
    for (int t = 0; t < 2; ++t) {
        logits_kernel<<<dim3(BB, 8), 256>>>(MSQ, OWT, out_b, Y);
        softmaxO_kernel<<<BB, 256>>>(Y, Y);
        gates_kernel<<<dim3(BB, 3), 256>>>(Y, OOO, QH, HHH, MSQ,
                                           WTAI, WTAH, ans_b_ih, ans_b_hh, GIA, GHA);
        combine_kernel<<<BB, 256>>>(GIA, GHA, MSQ, MSQ);
    }
    logits_kernel<<<dim3(BB, 8), 256>>>(MSQ, OWT, out_b, Y);
    softmaxO_kernel<<<BB, 256>>>(Y, out);
}

// round 14
// speedup vs baseline: 1.5830x; 1.0877x over previous
#include <cuda_runtime.h>
#include <math.h>
#include <stdint.h>

// Problem constants
#define BB   32
#define SSL  1024
#define SQQ  32
#define NNN  128
#define DINN 128
#define HHH  256
#define AAA  100
#define OOO  2000
#define G3H  768
#define FEAT 1794   // 7*H + 2
#define CLUSTER 8

// ---------------- scratch offsets (floats) in one big device buffer ----------
#define OFF_GI    0UL          // 1024*32*768  [t][b][row]
#define OFF_GIQ   25165824UL   // 32*32*768
#define OFF_COUT  25968640UL   // 1024*32*256  [t][b][k]
#define OFF_QOUT  34357248UL   // 32*32*256
#define OFF_QH    34619392UL   // 32*256
#define OFF_HTC   34627584UL   // 32*256
#define OFF_CSEL  34635776UL   // 32*128*256
#define OFF_CW    35684352UL   // 32*128*256
#define OFF_T0    36741120UL   // 4096*100
#define OFF_M     37150720UL   // 32*256
#define OFF_SC    37158912UL   // 4096
#define OFF_P     37163008UL   // 4096
#define OFF_E     37167104UL   // 32*256
#define OFF_MSQ   37175296UL   // 32*256
#define OFF_Y     37183488UL   // 32*2000
#define OFF_W1T   37247488UL   // 1794*128
#define OFF_WTAI  37480320UL   // 2256*768
#define OFF_WTAH  39212928UL   // 256*768
#define OFF_WTMI  39409536UL   // 256*768
#define OFF_WTMH  39606144UL   // 256*768
#define OFF_OWT   39802752UL   // 256*2000
#define OFF_GIA   40314752UL   // 32*768
#define OFF_GHA   40339328UL   // 32*768
#define TOTALF    40363904UL

__device__ __align__(16) float g_buf[TOTALF];

// ---------------- packed f32x2 FMA helpers (sm_103a) -------------------------
__device__ __forceinline__ unsigned long long pk2(float x, float y) {
    unsigned long long r;
    asm("mov.b64 %0, {%1, %2};" : "=l"(r) : "f"(x), "f"(y));
    return r;
}
__device__ __forceinline__ float upsum(unsigned long long a, unsigned long long b) {
    float ax, ay, bx, by;
    asm("mov.b64 {%0, %1}, %2;" : "=f"(ax), "=f"(ay) : "l"(a));
    asm("mov.b64 {%0, %1}, %2;" : "=f"(bx), "=f"(by) : "l"(b));
    return (ax + ay) + (bx + by);
}
#define FMA2(acc, a, b) \
    asm("fma.rn.f32x2 %0, %1, %2, %0;" : "+l"(acc) : "l"(a), "l"(b))

// ---------------- cluster helpers ---------------------------------------------
__device__ __forceinline__ uint32_t smem_u32(const void* p) {
    uint32_t a;
    asm("{ .reg .u64 t; cvta.to.shared.u64 t, %1; cvt.u32.u64 %0, t; }"
        : "=r"(a) : "l"(p));
    return a;
}
__device__ __forceinline__ uint32_t cluster_rank() {
    uint32_t r;
    asm("mov.u32 %0, %%cluster_ctarank;" : "=r"(r));
    return r;
}
__device__ __forceinline__ uint32_t mapa_u32(uint32_t addr, uint32_t rank) {
    uint32_t r;
    asm("mapa.shared::cluster.u32 %0, %1, %2;" : "=r"(r) : "r"(addr), "r"(rank));
    return r;
}
__device__ __forceinline__ void st_cluster_f32(uint32_t addr, float v) {
    asm volatile("st.shared::cluster.f32 [%0], %1;" :: "r"(addr), "f"(v) : "memory");
}
__device__ __forceinline__ void cluster_sync() {
    asm volatile("barrier.cluster.arrive.aligned;" ::: "memory");
    asm volatile("barrier.cluster.wait.aligned;" ::: "memory");
}

// ---------------- gi = x @ w_ih^T + b_ih  ->  out[t][b][row] ------------------
__global__ void __launch_bounds__(256) gi_kernel(
    const float* __restrict__ x, const float* __restrict__ w,
    const float* __restrict__ bias, float* __restrict__ out, int S)
{
    const int t = blockIdx.x;
    const int rbase = blockIdx.y * 192;
    __shared__ float4 xs4[32][33];    // [b][k4]
    __shared__ float  tile[192][33];  // [rr][b]
    for (int idx = threadIdx.x; idx < 1024; idx += 256) {
        int b = idx >> 5, k4 = idx & 31;
        xs4[b][k4] = __ldg(((const float4*)x) + ((size_t)b * S + t) * 32 + k4);
    }
    __syncthreads();
    const int b = threadIdx.x & 31, w0 = threadIdx.x >> 5;
    for (int r = rbase + w0 * 4; r < rbase + 192; r += 32) {
        const float4* wr0 = (const float4*)(w + (size_t)r * DINN);
        const float4* wr1 = wr0 + 32;
        const float4* wr2 = wr0 + 64;
        const float4* wr3 = wr0 + 96;
        float s[4][4];
        #pragma unroll
        for (int i = 0; i < 4; ++i)
            #pragma unroll
            for (int jj = 0; jj < 4; ++jj) s[i][jj] = 0.f;
        #pragma unroll
        for (int k4 = 0; k4 < 32; ++k4) {
            float4 xv = xs4[b][k4];
            float4 w0v = __ldg(wr0 + k4), w1v = __ldg(wr1 + k4);
            float4 w2v = __ldg(wr2 + k4), w3v = __ldg(wr3 + k4);
            s[0][0] += w0v.x * xv.x; s[0][1] += w0v.y * xv.y; s[0][2] += w0v.z * xv.z; s[0][3] += w0v.w * xv.w;
            s[1][0] += w1v.x * xv.x; s[1][1] += w1v.y * xv.y; s[1][2] += w1v.z * xv.z; s[1][3] += w1v.w * xv.w;
            s[2][0] += w2v.x * xv.x; s[2][1] += w2v.y * xv.y; s[2][2] += w2v.z * xv.z; s[2][3] += w2v.w * xv.w;
            s[3][0] += w3v.x * xv.x; s[3][1] += w3v.y * xv.y; s[3][2] += w3v.z * xv.z; s[3][3] += w3v.w * xv.w;
        }
        #pragma unroll
        for (int i = 0; i < 4; ++i)
            tile[r - rbase + i][b] =
                __ldg(bias + r + i) + (s[i][0] + s[i][1]) + (s[i][2] + s[i][3]);
    }
    __syncthreads();
    for (int idx = threadIdx.x; idx < 192 * 32; idx += 256) {
        int bb = idx / 192, rr = idx % 192;
        out[((size_t)t * BB + bb) * G3H + rbase + rr] = tile[rr][bb];
    }
}

// ---------------- cluster GRU recurrence ---------------------------------------
// 16 clusters x 8 CTAs x 192 threads. Cluster c owns batches {2c, 2c+1};
// rank r owns h columns [32r, 32r+32). Weights in registers; h ping-pongs in
// smem; new h DSMEM-broadcast. barrier.cluster arrive/wait SPLIT: cout store +
// gi prefetch execute inside the arrive->wait window (off the critical path).
__global__ void __launch_bounds__(192, 1) __cluster_dims__(CLUSTER, 1, 1)
rec_kernel(const float* __restrict__ gi, const float* __restrict__ whh,
           const float* __restrict__ bhh, int S,
           const float* __restrict__ h0,
           float* __restrict__ cout, float* __restrict__ finalh)
{
    __shared__ __align__(16) float hbuf[2][2][HHH];   // [pp][b][k]
    __shared__ float part[3][2][2][32];               // [g][kh][b][col]

    const int tid = threadIdx.x;
    const int w = tid >> 5, lane = tid & 31;
    const int g = w >> 1, kh = w & 1;                 // gate, k-half
    const uint32_t rank = cluster_rank();
    const int cid = blockIdx.x / CLUSTER;
    const int bg0 = cid * 2;
    const int colg = (int)rank * 32 + lane;

    // weights -> registers: row (g*256 + colg), half kh
    float4 wreg[32];
    {
        const float4* src = (const float4*)(whh + ((size_t)g * HHH + colg) * HHH + kh * 128);
        #pragma unroll
        for (int i = 0; i < 32; ++i) wreg[i] = __ldg(src + i);
    }

    int cb = 0, ccolg = 0;
    float bh0 = 0.f, bh1 = 0.f, bh2 = 0.f;
    if (tid < 64) {
        cb = tid >> 5;
        ccolg = (int)rank * 32 + (tid & 31);
        bh0 = __ldg(bhh + 0 * HHH + ccolg);
        bh1 = __ldg(bhh + 1 * HHH + ccolg);
        bh2 = __ldg(bhh + 2 * HHH + ccolg);
    }

    for (int i = tid; i < 2 * HHH; i += 192) {
        int b = i >> 8, k = i & 255;
        hbuf[0][b][k] = h0[(bg0 + b) * HHH + k];
    }

    float gr = 0.f, gz = 0.f, gn = 0.f;
    if (tid < 64) {
        const float* gp = gi + ((size_t)0 * BB + bg0 + cb) * G3H;
        gr = __ldcg(gp + 0 * HHH + ccolg);
        gz = __ldcg(gp + 1 * HHH + ccolg);
        gn = __ldcg(gp + 2 * HHH + ccolg);
    }
    __syncthreads();
    cluster_sync();

    int pp = 0;
    for (int t = 0; t < S; ++t) {
        unsigned long long a0x = 0, a0y = 0, a1x = 0, a1y = 0;
        const float4* hb0 = (const float4*)(hbuf[pp][0] + kh * 128);
        const float4* hb1 = (const float4*)(hbuf[pp][1] + kh * 128);
        #pragma unroll
        for (int k4 = 0; k4 < 32; ++k4) {
            float4 wv = wreg[k4];
            unsigned long long wxy = pk2(wv.x, wv.y), wzw = pk2(wv.z, wv.w);
            float4 h0v = hb0[k4];
            FMA2(a0x, wxy, pk2(h0v.x, h0v.y));
            FMA2(a0y, wzw, pk2(h0v.z, h0v.w));
            float4 h1v = hb1[k4];
            FMA2(a1x, wxy, pk2(h1v.x, h1v.y));
            FMA2(a1y, wzw, pk2(h1v.z, h1v.w));
        }
        part[g][kh][0][lane] = upsum(a0x, a0y);
        part[g][kh][1][lane] = upsum(a1x, a1y);
        __syncthreads();

        float hnew = 0.f;
        if (tid < 64) {
            int ccol = tid & 31;
            float hr = part[0][0][cb][ccol] + part[0][1][cb][ccol] + bh0;
            float hz = part[1][0][cb][ccol] + part[1][1][cb][ccol] + bh1;
            float hn = part[2][0][cb][ccol] + part[2][1][cb][ccol] + bh2;
            float rg = 1.f / (1.f + expf(-(gr + hr)));
            float zg = 1.f / (1.f + expf(-(gz + hz)));
            float ng = tanhf(gn + rg * hn);
            float hold = hbuf[pp][cb][ccolg];
            hnew = (1.f - zg) * ng + zg * hold;
            // DSMEM broadcast FIRST (critical path for other CTAs)
            uint32_t laddr = smem_u32(&hbuf[pp ^ 1][cb][ccolg]);
            #pragma unroll
            for (uint32_t p = 0; p < CLUSTER; ++p)
                st_cluster_f32(mapa_u32(laddr, p), hnew);
        }
        asm volatile("barrier.cluster.arrive.aligned;" ::: "memory");
        // inside arrive->wait window: global store + next gi prefetch
        if (tid < 64) {
            cout[((size_t)t * BB + bg0 + cb) * HHH + ccolg] = hnew;
            if (t == S - 1) finalh[(bg0 + cb) * HHH + ccolg] = hnew;
            if (t + 1 < S) {
                const float* gp = gi + ((size_t)(t + 1) * BB + bg0 + cb) * G3H;
                gr = __ldcg(gp + 0 * HHH + ccolg);
                gz = __ldcg(gp + 1 * HHH + ccolg);
                gn = __ldcg(gp + 2 * HHH + ccolg);
            }
        }
        asm volatile("barrier.cluster.wait.aligned;" ::: "memory");
        pp ^= 1;
    }
}

// ---------------- transpose src[R][K] -> dst[K][R] ---------------------------
__global__ void transpose_kernel(const float* __restrict__ src, float* __restrict__ dst,
                                 int R, int K)
{
    __shared__ float tile[32][33];
    int k0 = blockIdx.x * 32, r0 = blockIdx.y * 32;
    int lx = threadIdx.x, ly = threadIdx.y;   // 32 x 8
    for (int i = ly; i < 32; i += 8) {
        int r = r0 + i, k = k0 + lx;
        tile[i][lx] = (r < R && k < K) ? src[(size_t)r * K + k] : 0.f;
    }
    __syncthreads();
    for (int i = ly; i < 32; i += 8) {
        int k = k0 + i, r = r0 + lx;
        if (k < K && r < R) dst[(size_t)k * R + r] = tile[lx][i];
    }
}

// ---------------- transpose att_w1 -> w1t[f][a] padded to 128 ----------------
__global__ void w1t_kernel(const float* __restrict__ w1, float* __restrict__ w1t)
{
    int idx = blockIdx.x * 256 + threadIdx.x;
    if (idx >= FEAT * 128) return;
    int f = idx >> 7, a = idx & 127;
    w1t[idx] = (a < AAA) ? w1[a * FEAT + f] : 0.f;
}

// ---------------- gather c_sel (from [t][b][k]) + cw = c_sel @ att_weight ----
__global__ void __launch_bounds__(256) cwgather_kernel(
    const float* __restrict__ cout, const int* __restrict__ cindex,
    const float* __restrict__ attw, float* __restrict__ csel, float* __restrict__ cw)
{
    const int r0 = blockIdx.x * 16;
    const int b  = r0 >> 7;
    const int tid = threadIdx.x;
    __shared__ float cs[16][HHH];
    __shared__ int ti[16];
    if (tid < 16) ti[tid] = cindex[b * NNN + ((r0 + tid) & 127)];
    __syncthreads();
    for (int idx = tid; idx < 16 * HHH; idx += 256) {
        int r = idx >> 8, k = idx & 255;
        float v = cout[((size_t)ti[r] * BB + b) * HHH + k];
        cs[r][k] = v;
        csel[(size_t)(r0 + r) * HHH + k] = v;
    }
    __syncthreads();
    float acc[16];
    #pragma unroll
    for (int r = 0; r < 16; ++r) acc[r] = 0.f;
    const int jcol = tid;
    for (int k = 0; k < HHH; ++k) {
        float wk = __ldg(attw + k * HHH + jcol);
        #pragma unroll
        for (int r = 0; r < 16; ++r) acc[r] += cs[r][k] * wk;
    }
    #pragma unroll
    for (int r = 0; r < 16; ++r) cw[(size_t)(r0 + r) * HHH + jcol] = acc[r];
}

// ---------------- attention projection (dot + bterm folded in) ---------------
// USEC (T0 precompute): acc = b1 + v.w1[qh block] + dotq*w1[1792] + c-terms
// SCORE (hop):          acc = T0 + v.w1[m block] + dotm*w1[1793] + c-terms -> scores
template <bool USEC, bool SCORE>
__global__ void __launch_bounds__(128) attproj_kernel(
    const float* __restrict__ csel, const float* __restrict__ cw,
    const float* __restrict__ vvec, const float* __restrict__ base,
    const float* __restrict__ w1t, const float* __restrict__ b1, int offb,
    int o2, int o3, int dotcol,
    const float* __restrict__ w2, const float* __restrict__ b2,
    float* __restrict__ outT0, float* __restrict__ outScores)
{
    const int r0 = blockIdx.x * 16;
    const int b  = r0 >> 7;
    const int tid = threadIdx.x;
    __shared__ float cs[16][HHH];
    __shared__ float cwS[16][HHH];
    __shared__ float vs[HHH];
    __shared__ float tvs[16][128];
    __shared__ float dred[16][4];
    __shared__ float dotS[16];
    for (int idx = tid; idx < 16 * HHH; idx += 128) {
        int r = idx >> 8, k = idx & 255;
        cs[r][k]  = csel[(size_t)(r0 + r) * HHH + k];
        cwS[r][k] = cw[(size_t)(r0 + r) * HHH + k];
    }
    for (int idx = tid; idx < HHH; idx += 128) vs[idx] = vvec[b * HHH + idx];
    __syncthreads();

    const int a = tid, wq = tid >> 5, ln = tid & 31;

    // row dots: dotS[r] = cw[r] . v
    #pragma unroll
    for (int r = 0; r < 16; ++r) {
        float v = cwS[r][a] * vs[a] + cwS[r][a + 128] * vs[a + 128];
        #pragma unroll
        for (int o = 16; o; o >>= 1) v += __shfl_xor_sync(0xffffffffu, v, o);
        if (ln == 0) dred[r][wq] = v;
    }
    __syncthreads();
    if (tid < 16) dotS[tid] = dred[tid][0] + dred[tid][1] + dred[tid][2] + dred[tid][3];
    __syncthreads();

    const bool va = a < AAA;
    // bterm inline: (b1?) + v . w1t_cols(offb..offb+256)
    float bt = (USEC && va) ? __ldg(b1 + a) : 0.f;
    {
        float t0 = 0, t1 = 0, t2 = 0, t3 = 0;
        for (int k = 0; k < HHH; k += 4) {
            t0 += vs[k]     * w1t[(offb + k) * 128 + a];
            t1 += vs[k + 1] * w1t[(offb + k + 1) * 128 + a];
            t2 += vs[k + 2] * w1t[(offb + k + 2) * 128 + a];
            t3 += vs[k + 3] * w1t[(offb + k + 3) * 128 + a];
        }
        bt += (t0 + t1) + (t2 + t3);
    }
    float wd = w1t[dotcol * 128 + a];
    float acc[16];
    #pragma unroll
    for (int r = 0; r < 16; ++r) {
        float v0 = bt + dotS[r] * wd;
        if (SCORE && va) v0 += base[(size_t)(r0 + r) * AAA + a];
        acc[r] = v0;
    }
    for (int k = 0; k < HHH; ++k) {
        float f1 = USEC ? w1t[k * 128 + a] : 0.f;
        float f2 = w1t[(o2 + k) * 128 + a];
        float f3 = w1t[(o3 + k) * 128 + a];
        float vk = vs[k];
        #pragma unroll
        for (int r = 0; r < 16; ++r) {
            float c = cs[r][k];
            acc[r] += (c * vk) * f2 + fabsf(c - vk) * f3;
            if (USEC) acc[r] += c * f1;
        }
    }
    if (!SCORE) {
        if (va) {
            #pragma unroll
            for (int r = 0; r < 16; ++r) outT0[(size_t)(r0 + r) * AAA + a] = acc[r];
        }
    } else {
        float w2a = va ? __ldg(w2 + a) : 0.f;
        #pragma unroll
        for (int r = 0; r < 16; ++r) tvs[r][a] = va ? tanhf(acc[r]) * w2a : 0.f;
        __syncthreads();
        #pragma unroll
        for (int rr = 0; rr < 4; ++rr) {
            int row = wq * 4 + rr;
            float s = tvs[row][ln] + tvs[row][ln + 32] + tvs[row][ln + 64] + tvs[row][ln + 96];
            #pragma unroll
            for (int o = 16; o; o >>= 1) s += __shfl_xor_sync(0xffffffffu, s, o);
            if (ln == 0) outScores[r0 + row] = s + __ldg(b2);
        }
    }
}

// ---------------- masked softmax over N=128 ----------------------------------
__global__ void softmaxN_kernel(const float* __restrict__ scores, const int* __restrict__ lenc,
                                float* __restrict__ p, float* __restrict__ attout)
{
    const int b = blockIdx.x, n = threadIdx.x;
    const int lc = lenc[b];
    __shared__ float red[4];
    float s = (n < lc) ? scores[b * NNN + n] : -1e30f;
    float m = s;
    for (int o = 16; o; o >>= 1) m = fmaxf(m, __shfl_xor_sync(0xffffffffu, m, o));
    if ((n & 31) == 0) red[n >> 5] = m;
    __syncthreads();
    m = fmaxf(fmaxf(red[0], red[1]), fmaxf(red[2], red[3]));
    __syncthreads();
    float ev = (n < lc) ? expf(s - m) : 0.f;
    float sum = ev;
    for (int o = 16; o; o >>= 1) sum += __shfl_xor_sync(0xffffffffu, sum, o);
    if ((n & 31) == 0) red[n >> 5] = sum;
    __syncthreads();
    sum = red[0] + red[1] + red[2] + red[3];
    float pv = ev / sum;
    p[b * NNN + n] = pv;
    attout[b * NNN + n] = pv;
}

// ---------------- e[b][k] = sum_n csel[b][n][k] * p[b][n] --------------------
__global__ void __launch_bounds__(256) e_kernel(const float* __restrict__ csel,
                                                const float* __restrict__ p,
                                                float* __restrict__ e)
{
    const int b = blockIdx.x, k = threadIdx.x;
    __shared__ float ps[NNN];
    if (k < NNN) ps[k] = p[b * NNN + k];
    __syncthreads();
    float a0 = 0, a1 = 0;
    for (int n = 0; n < NNN; n += 2) {
        a0 += csel[(size_t)((b << 7) + n) * HHH + k] * ps[n];
        a1 += csel[(size_t)((b << 7) + n + 1) * HHH + k] * ps[n + 1];
    }
    e[b * HHH + k] = a0 + a1;
}

// ---------------- GRU gates via transposed weights ---------------------------
__global__ void __launch_bounds__(256) gates_kernel(
    const float* __restrict__ x1, int k1, const float* __restrict__ x2, int k2,
    const float* __restrict__ h, const float* __restrict__ wti,
    const float* __restrict__ wth, const float* __restrict__ bih,
    const float* __restrict__ bhh, float* __restrict__ gia, float* __restrict__ gha)
{
    const int b = blockIdx.x, rc = blockIdx.y, tid = threadIdx.x;
    const int r = rc * 256 + tid;
    __shared__ float xs[2304];
    __shared__ float hsm[HHH];
    for (int i = tid; i < k1; i += 256) xs[i] = x1[(size_t)b * k1 + i];
    for (int i = tid; i < k2; i += 256) xs[k1 + i] = x2[(size_t)b * k2 + i];
    hsm[tid] = h[b * HHH + tid];
    __syncthreads();
    const int K = k1 + k2;
    float a0 = 0, a1 = 0, a2 = 0, a3 = 0;
    int k = 0;
    for (; k + 4 <= K; k += 4) {
        a0 += xs[k]     * wti[(size_t)k * G3H + r];
        a1 += xs[k + 1] * wti[(size_t)(k + 1) * G3H + r];
        a2 += xs[k + 2] * wti[(size_t)(k + 2) * G3H + r];
        a3 += xs[k + 3] * wti[(size_t)(k + 3) * G3H + r];
    }
    for (; k < K; ++k) a0 += xs[k] * wti[(size_t)k * G3H + r];
    gia[b * G3H + r] = __ldg(bih + r) + (a0 + a1) + (a2 + a3);
    float c0 = 0, c1 = 0, c2 = 0, c3 = 0;
    for (int kk = 0; kk < HHH; kk += 4) {
        c0 += hsm[kk]     * wth[(size_t)kk * G3H + r];
        c1 += hsm[kk + 1] * wth[(size_t)(kk + 1) * G3H + r];
        c2 += hsm[kk + 2] * wth[(size_t)(kk + 2) * G3H + r];
        c3 += hsm[kk + 3] * wth[(size_t)(kk + 3) * G3H + r];
    }
    gha[b * G3H + r] = __ldg(bhh + r) + (c0 + c1) + (c2 + c3);
}

__global__ void __launch_bounds__(256) combine_kernel(
    const float* __restrict__ gia, const float* __restrict__ gha,
    const float* __restrict__ h, float* __restrict__ hout)
{
    const int b = blockIdx.x, k = threadIdx.x;
    float rg = 1.f / (1.f + expf(-(gia[b * G3H + k] + gha[b * G3H + k])));
    float zg = 1.f / (1.f + expf(-(gia[b * G3H + HHH + k] + gha[b * G3H + HHH + k])));
    float ng = tanhf(gia[b * G3H + 2 * HHH + k] + rg * gha[b * G3H + 2 * HHH + k]);
    hout[b * HHH + k] = (1.f - zg) * ng + zg * h[b * HHH + k];
}

// ---------------- logits via transposed out_w --------------------------------
__global__ void __launch_bounds__(256) logits_kernel(
    const float* __restrict__ hv, const float* __restrict__ owt,
    const float* __restrict__ ob, float* __restrict__ y)
{
    const int b = blockIdx.x, tid = threadIdx.x;
    const int o = blockIdx.y * 256 + tid;
    __shared__ float ms[HHH];
    ms[tid] = hv[b * HHH + tid];
    __syncthreads();
    if (o >= OOO) return;
    float a0 = 0, a1 = 0, a2 = 0, a3 = 0;
    for (int k = 0; k < HHH; k += 4) {
        a0 += ms[k]     * owt[(size_t)k * OOO + o];
        a1 += ms[k + 1] * owt[(size_t)(k + 1) * OOO + o];
        a2 += ms[k + 2] * owt[(size_t)(k + 2) * OOO + o];
        a3 += ms[k + 3] * owt[(size_t)(k + 3) * OOO + o];
    }
    y[(size_t)b * OOO + o] = __ldg(ob + o) + (a0 + a1) + (a2 + a3);
}

// ---------------- softmax over O=2000 ----------------------------------------
__global__ void __launch_bounds__(256) softmaxO_kernel(const float* __restrict__ yin,
                                                       float* __restrict__ yout)
{
    const int b = blockIdx.x, tid = threadIdx.x;
    __shared__ float red[8];
    float m = -1e30f;
    for (int o = tid; o < OOO; o += 256) m = fmaxf(m, yin[(size_t)b * OOO + o]);
    for (int o = 16; o; o >>= 1) m = fmaxf(m, __shfl_xor_sync(0xffffffffu, m, o));
    if ((tid & 31) == 0) red[tid >> 5] = m;
    __syncthreads();
    m = red[0];
    #pragma unroll
    for (int i = 1; i < 8; ++i) m = fmaxf(m, red[i]);
    __syncthreads();
    float sum = 0.f;
    for (int o = tid; o < OOO; o += 256) sum += expf(yin[(size_t)b * OOO + o] - m);
    for (int o = 16; o; o >>= 1) sum += __shfl_xor_sync(0xffffffffu, sum, o);
    if ((tid & 31) == 0) red[tid >> 5] = sum;
    __syncthreads();
    sum = 0.f;
    #pragma unroll
    for (int i = 0; i < 8; ++i) sum += red[i];
    float inv = 1.f / sum;
    for (int o = tid; o < OOO; o += 256)
        yout[(size_t)b * OOO + o] = expf(yin[(size_t)b * OOO + o] - m) * inv;
}

// ------------------------------- launch --------------------------------------
extern "C" void kernel_launch(void* const* d_in, const int* in_sizes, int n_in,
                              void* d_out, int out_size)
{
    const float* c        = (const float*)d_in[0];
    const float* q        = (const float*)d_in[1];
    const float* i_state  = (const float*)d_in[2];
    const float* q_state  = (const float*)d_in[3];
    const float* in_w_ih  = (const float*)d_in[4];
    const float* in_w_hh  = (const float*)d_in[5];
    const float* in_b_ih  = (const float*)d_in[6];
    const float* in_b_hh  = (const float*)d_in[7];
    const float* qe_w_ih  = (const float*)d_in[8];
    const float* qe_w_hh  = (const float*)d_in[9];
    const float* qe_b_ih  = (const float*)d_in[10];
    const float* qe_b_hh  = (const float*)d_in[11];
    const float* att_weight = (const float*)d_in[12];
    const float* att_w1   = (const float*)d_in[13];
    const float* att_b1   = (const float*)d_in[14];
    const float* att_w2   = (const float*)d_in[15];
    const float* att_b2   = (const float*)d_in[16];
    const float* mem_w_ih = (const float*)d_in[17];
    const float* mem_w_hh = (const float*)d_in[18];
    const float* mem_b_ih = (const float*)d_in[19];
    const float* mem_b_hh = (const float*)d_in[20];
    const float* out_w    = (const float*)d_in[21];
    const float* out_b    = (const float*)d_in[22];
    const float* ans_w_ih = (const float*)d_in[23];
    const float* ans_w_hh = (const float*)d_in[24];
    const float* ans_b_ih = (const float*)d_in[25];
    const float* ans_b_hh = (const float*)d_in[26];
    const int*   c_index  = (const int*)d_in[27];
    const int*   len_c    = (const int*)d_in[28];
    float* out = (float*)d_out;

    float* gb = nullptr;
    cudaGetSymbolAddress((void**)&gb, g_buf);

    float* GI   = gb + OFF_GI;
    float* GIQ  = gb + OFF_GIQ;
    float* COUT = gb + OFF_COUT;
    float* QOUT = gb + OFF_QOUT;
    float* QH   = gb + OFF_QH;
    float* HTC  = gb + OFF_HTC;
    float* CSEL = gb + OFF_CSEL;
    float* CW   = gb + OFF_CW;
    float* T0   = gb + OFF_T0;
    float* M    = gb + OFF_M;
    float* SC   = gb + OFF_SC;
    float* P    = gb + OFF_P;
    float* E    = gb + OFF_E;
    float* MSQ  = gb + OFF_MSQ;
    float* Y    = gb + OFF_Y;
    float* W1T  = gb + OFF_W1T;
    float* WTAI = gb + OFF_WTAI;
    float* WTAH = gb + OFF_WTAH;
    float* WTMI = gb + OFF_WTMI;
    float* WTMH = gb + OFF_WTMH;
    float* OWT  = gb + OFF_OWT;
    float* GIA  = gb + OFF_GIA;
    float* GHA  = gb + OFF_GHA;

    dim3 tblk(32, 8);

    // rec_kernel (context) placed at launch #4 — observed ncu capture slot.
    gi_kernel<<<dim3(SSL, 4), 256>>>(c, in_w_ih, in_b_ih, GI, SSL);                      // 1
    w1t_kernel<<<(FEAT * 128 + 255) / 256, 256>>>(att_w1, W1T);                          // 2
    transpose_kernel<<<dim3((2256 + 31) / 32, 24), tblk>>>(ans_w_ih, WTAI, 768, 2256);   // 3
    rec_kernel<<<128, 192>>>(GI, in_w_hh, in_b_hh, SSL, i_state, COUT, HTC);             // 4 <- ncu
    transpose_kernel<<<dim3(8, 24), tblk>>>(ans_w_hh, WTAH, 768, 256);                   // 5
    transpose_kernel<<<dim3(8, 24), tblk>>>(mem_w_ih, WTMI, 768, 256);                   // 6
    transpose_kernel<<<dim3(8, 24), tblk>>>(mem_w_hh, WTMH, 768, 256);                   // 7
    transpose_kernel<<<dim3(8, (2000 + 31) / 32), tblk>>>(out_w, OWT, 2000, 256);        // 8

    // ---- query GRU ----
    gi_kernel<<<dim3(SQQ, 4), 256>>>(q, qe_w_ih, qe_b_ih, GIQ, SQQ);
    rec_kernel<<<128, 192>>>(GIQ, qe_w_hh, qe_b_hh, SQQ, q_state, QOUT, QH);

    // ---- attention prep (dot + bterm folded into attproj) ----
    cwgather_kernel<<<BB * NNN / 16, 256>>>(COUT, c_index, att_weight, CSEL, CW);
    attproj_kernel<true, false><<<BB * NNN / 16, 128>>>(
        CSEL, CW, QH, nullptr, W1T, att_b1, 512, 768, 1280, 1792,
        nullptr, nullptr, T0, nullptr);

    // ---- 3 memory hops (hop 0 reads m = QH directly; no copies) ----
    for (int hop = 0; hop < 3; ++hop) {
        const float* Mh = (hop == 0) ? QH : M;
        attproj_kernel<false, true><<<BB * NNN / 16, 128>>>(
            CSEL, CW, Mh, T0, W1T, nullptr, 256, 1024, 1536, 1793,
            att_w2, att_b2, nullptr, SC);
        softmaxN_kernel<<<BB, NNN>>>(SC, len_c, P, out + BB * OOO + hop * BB * NNN);
        e_kernel<<<BB, HHH>>>(CSEL, P, E);
        gates_kernel<<<dim3(BB, 3), 256>>>(E, HHH, nullptr, 0, Mh,
                                           WTMI, WTMH, mem_b_ih, mem_b_hh, GIA, GHA);
        combine_kernel<<<BB, 256>>>(GIA, GHA, Mh, M);
    }

    // ---- answer loop (t=0 reads M, writes MSQ; no copy) ----
    for (int t = 0; t < 2; ++t) {
        const float* Ms = (t == 0) ? M : MSQ;
        logits_kernel<<<dim3(BB, 8), 256>>>(Ms, OWT, out_b, Y);
        softmaxO_kernel<<<BB, 256>>>(Y, Y);
        gates_kernel<<<dim3(BB, 3), 256>>>(Y, OOO, QH, HHH, Ms,
                                           WTAI, WTAH, ans_b_ih, ans_b_hh, GIA, GHA);
        combine_kernel<<<BB, 256>>>(GIA, GHA, Ms, MSQ);
    }
    logits_kernel<<<dim3(BB, 8), 256>>>(MSQ, OWT, out_b, Y);
    softmaxO_kernel<<<BB, 256>>>(Y, out);
}